// round 6
// baseline (speedup 1.0000x reference)
#include <cuda_runtime.h>
#include <cstdint>

// Problem constants
#define Bsz   1024
#define Tt    128
#define DIN   256
#define Hh    128
#define NG    512          // 4*H gates
#define KTOT  896          // DIN + H + 4*H (x | h | 4 shuffled-h via folded read)
#define NBLK  128          // persistent grid size (8 u-tiles x 16 batch-tiles)
#define BK    64
#define NCHUNK (KTOT / BK) // 14
#define LDC   68           // smem row stride (68 % 32 == 4 -> conflict-free frags)

// ---------------- device scratch (static, no allocations) ----------------
__device__ float d_WcT[NG * KTOT];      // [n][k] combined weight
__device__ float d_bias[NG];
__device__ float d_add0[NG];            // t==0 read-vector bias
__device__ float d_memsm[Hh * Hh];      // softmax(memory, axis=0)
__device__ float d_hA[Bsz * Hh];        // h ping-pong
__device__ float d_hB[Bsz * Hh];
__device__ float d_S[Bsz * Hh];         // sum over t of h
__device__ float d_f0[2 * Hh];          // fc_w direct-h part
__device__ float d_gv[2 * 4 * Hh];      // fc_w read part folded through mem_sm
__device__ unsigned g_bar;              // grid barrier counter

// ---------------- helpers ----------------
__device__ __forceinline__ float to_tf32(float x) {
    unsigned u;
    asm("cvt.rna.tf32.f32 %0, %1;" : "=r"(u) : "f"(x));
    return __uint_as_float(u);
}

__device__ __forceinline__ void mma8(float* d, const float* a, float b0f, float b1f) {
    asm volatile(
        "mma.sync.aligned.m16n8k8.row.col.f32.tf32.tf32.f32 "
        "{%0,%1,%2,%3}, {%4,%5,%6,%7}, {%8,%9}, {%0,%1,%2,%3};\n"
        : "+f"(d[0]), "+f"(d[1]), "+f"(d[2]), "+f"(d[3])
        : "r"(__float_as_uint(a[0])), "r"(__float_as_uint(a[1])),
          "r"(__float_as_uint(a[2])), "r"(__float_as_uint(a[3])),
          "r"(__float_as_uint(b0f)), "r"(__float_as_uint(b1f)));
}

__device__ __forceinline__ void load32(const float* p, float4* r) {
#pragma unroll
    for (int i = 0; i < 8; i++) r[i] = ((const float4*)p)[i];
}

__device__ __forceinline__ void cvt_store32(float* dst, const float4* r) {
#pragma unroll
    for (int i = 0; i < 8; i++) {
        dst[4 * i + 0] = to_tf32(r[i].x);
        dst[4 * i + 1] = to_tf32(r[i].y);
        dst[4 * i + 2] = to_tf32(r[i].z);
        dst[4 * i + 3] = to_tf32(r[i].w);
    }
}

// Source pointer for Hcat[b][k0 .. k0+31]; segment boundaries at multiples of 128,
// k0 is a multiple of 32 so a 32-float run stays inside one segment.
__device__ __forceinline__ const float* a_src(const float* __restrict__ x,
                                              const float* __restrict__ hp,
                                              int b, int t, int k0) {
    int seg = k0 >> 7;                     // 0,1: x | 2: h | 3..6: shuffled h
    if (seg < 2)  return x + (b * Tt + t) * DIN + k0;
    if (seg == 2) return hp + b * Hh + (k0 - 256);
    int j  = seg - 3;
    int bb = (4 * b + j) & (Bsz - 1);
    return hp + bb * Hh + (k0 - 384 - 128 * j);
}

// ---------------- setup kernels ----------------

// softmax over memory slots (axis=0): one block per column w
__global__ void softmax_kernel(const float* __restrict__ memory) {
    int w = blockIdx.x;
    int m = threadIdx.x;
    __shared__ float red[Hh];
    float v = memory[m * Hh + w];
    red[m] = v;
    __syncthreads();
    for (int s = 64; s > 0; s >>= 1) {
        if (m < s) red[m] = fmaxf(red[m], red[m + s]);
        __syncthreads();
    }
    float mx = red[0];
    __syncthreads();
    float e = expf(v - mx);
    red[m] = e;
    __syncthreads();
    for (int s = 64; s > 0; s >>= 1) {
        if (m < s) red[m] += red[m + s];
        __syncthreads();
    }
    d_memsm[m * Hh + w] = e / red[0];
}

// Build WcT[n][k]
__global__ void build_wct_kernel(const float* __restrict__ W_ih,
                                 const float* __restrict__ W_hh) {
    int idx = blockIdx.x * blockDim.x + threadIdx.x;
    if (idx >= NG * KTOT) return;
    int n = idx / KTOT, k = idx % KTOT;
    float v;
    if (k < 256) {
        v = W_ih[n * 768 + k];
    } else if (k < 384) {
        v = W_hh[n * Hh + (k - 256)];
    } else {
        int j = (k - 384) >> 7, w = (k - 384) & 127;
        const float* wr = W_ih + n * 768 + 256 + 128 * j;
        float s = 0.f;
#pragma unroll 8
        for (int m = 0; m < 128; m++) s += wr[m] * d_memsm[m * Hh + w];
        v = s;
    }
    d_WcT[idx] = v;
}

// warp-per-dot-product version of the misc setup (bias/add0/f0/gv)
__global__ void build_misc2_kernel(const float* __restrict__ W_ih,
                                   const float* __restrict__ rv0,
                                   const float* __restrict__ b_ih,
                                   const float* __restrict__ b_hh,
                                   const float* __restrict__ fc_w) {
    int gw   = (blockIdx.x * blockDim.x + threadIdx.x) >> 5;
    int lane = threadIdx.x & 31;
    if (gw < NG) {
        const float* wr = W_ih + gw * 768 + 256;
        float s = 0.f;
        for (int k = lane; k < 512; k += 32) s += rv0[k] * wr[k];
#pragma unroll
        for (int o = 16; o > 0; o >>= 1) s += __shfl_down_sync(0xffffffffu, s, o);
        if (lane == 0) {
            d_add0[gw] = s;
            d_bias[gw] = b_ih[gw] + b_hh[gw];
        }
    } else if (gw < NG + 1024) {
        int i2 = gw - NG;                         // [o][j][w]
        int o = i2 >> 9, j = (i2 >> 7) & 3, w = i2 & 127;
        float s = 0.f;
        for (int m = lane; m < 128; m += 32)
            s += d_memsm[m * Hh + w] * fc_w[o * 640 + 128 + 128 * j + m];
#pragma unroll
        for (int o2 = 16; o2 > 0; o2 >>= 1) s += __shfl_down_sync(0xffffffffu, s, o2);
        if (lane == 0) d_gv[i2] = s;
    } else if (gw < NG + 1024 + 8) {
        int i2 = (gw - NG - 1024) * 32 + lane;    // 256 values
        d_f0[i2] = fc_w[(i2 >> 7) * 640 + (i2 & 127)];
    }
}

__global__ void zero_state_kernel() {
    int i = blockIdx.x * blockDim.x + threadIdx.x;
    if (i < Bsz * Hh) {
        d_hA[i] = 0.f;
        d_hB[i] = 0.f;
    }
    if (i == 0) g_bar = 0u;
}

// ---------------- persistent fused recurrence kernel ----------------
// Grid (8, 16) = 128 blocks, 128 threads each. Block owns batches [64*by, +64)
// and h-units [16*bx, +16) (i.e. gate columns {u, 128+u, 256+u, 384+u}).
// c and S live in registers for the whole T loop; h ping-pongs through global.
__global__ void __launch_bounds__(128) dnc_persistent(const float* __restrict__ x) {
    extern __shared__ float sm[];
    float* As     = sm;                       // [2][64][LDC]
    float* Bs     = sm + 2 * 64 * LDC;        // [2][64][LDC]
    float* Cs     = sm;                       // aliases As buffer 0 (4352 floats)
    float* bias_s = sm + 4 * 64 * LDC;        // 64
    float* add0_s = bias_s + 64;              // 64

    const int tid  = threadIdx.x;
    const int warp = tid >> 5, lane = tid & 31;
    const int wm = (warp >> 1) * 32, wn = (warp & 1) * 32;
    const int g  = lane >> 2,  t4 = lane & 3;
    const int arow = tid >> 1, acol = (tid & 1) * 32;
    const int ui = blockIdx.x;                // 0..7
    const int b0 = blockIdx.y * 64;

    if (tid < 64) {
        int ng = (tid >> 4) * 128 + ui * 16 + (tid & 15);
        bias_s[tid] = d_bias[ng];
        add0_s[tid] = d_add0[ng];
    }
    // B loader: local row arow -> global gate column
    const int brow_g = (arow >> 4) * 128 + ui * 16 + (arow & 15);
    const float* wrow = d_WcT + brow_g * KTOT + acol;

    float c_st[8], S_st[8];
#pragma unroll
    for (int r = 0; r < 8; r++) { c_st[r] = 0.f; S_st[r] = 0.f; }

    const int b_l = tid >> 1, uh = tid & 1;   // update-phase ownership

#pragma unroll 1
    for (int t = 0; t < Tt; t++) {
        const float* hp = (t & 1) ? d_hB : d_hA;
        float*       hw = (t & 1) ? d_hA : d_hB;

        float acc[2][4][4];
#pragma unroll
        for (int i = 0; i < 2; i++)
#pragma unroll
            for (int j = 0; j < 4; j++)
#pragma unroll
                for (int q = 0; q < 4; q++) acc[i][j][q] = 0.f;

        float4 ra[8], rb[8];

        // prologue: chunk 0
        load32(a_src(x, hp, b0 + arow, t, acol), ra);
        load32(wrow, rb);
        cvt_store32(&As[arow * LDC + acol], ra);
        cvt_store32(&Bs[arow * LDC + acol], rb);
        __syncthreads();

#pragma unroll 1
        for (int ck = 0; ck < NCHUNK; ck++) {
            int cur = ck & 1;
            if (ck + 1 < NCHUNK) {
                load32(a_src(x, hp, b0 + arow, t, (ck + 1) * BK + acol), ra);
                load32(wrow + (ck + 1) * BK, rb);
            }
            const float* Ac = As + cur * 64 * LDC;
            const float* Bc = Bs + cur * 64 * LDC;
#pragma unroll
            for (int ks = 0; ks < 8; ks++) {
                float afr[2][4];
#pragma unroll
                for (int mi = 0; mi < 2; mi++) {
                    int mr = wm + mi * 16;
                    afr[mi][0] = Ac[(mr + g) * LDC + ks * 8 + t4];
                    afr[mi][1] = Ac[(mr + g + 8) * LDC + ks * 8 + t4];
                    afr[mi][2] = Ac[(mr + g) * LDC + ks * 8 + t4 + 4];
                    afr[mi][3] = Ac[(mr + g + 8) * LDC + ks * 8 + t4 + 4];
                }
#pragma unroll
                for (int ni = 0; ni < 4; ni++) {
                    int nr = wn + ni * 8;
                    float bf0 = Bc[(nr + g) * LDC + ks * 8 + t4];
                    float bf1 = Bc[(nr + g) * LDC + ks * 8 + t4 + 4];
                    mma8(acc[0][ni], afr[0], bf0, bf1);
                    mma8(acc[1][ni], afr[1], bf0, bf1);
                }
            }
            __syncthreads();
            if (ck + 1 < NCHUNK) {
                cvt_store32(&As[(cur ^ 1) * 64 * LDC + arow * LDC + acol], ra);
                cvt_store32(&Bs[(cur ^ 1) * 64 * LDC + arow * LDC + acol], rb);
                __syncthreads();
            }
        }

        // write C tile to smem (Cs aliases As buffer 0; last compute used buffer 1)
#pragma unroll
        for (int mi = 0; mi < 2; mi++) {
#pragma unroll
            for (int ni = 0; ni < 4; ni++) {
                int r    = wm + mi * 16 + g;
                int cidx = wn + ni * 8 + 2 * t4;
                Cs[r * LDC + cidx]           = acc[mi][ni][0];
                Cs[r * LDC + cidx + 1]       = acc[mi][ni][1];
                Cs[(r + 8) * LDC + cidx]     = acc[mi][ni][2];
                Cs[(r + 8) * LDC + cidx + 1] = acc[mi][ni][3];
            }
        }
        __syncthreads();

        // fused LSTM update: thread owns (b_l, 8 u's), c/S in registers
        {
            float hv[8];
#pragma unroll
            for (int r2 = 0; r2 < 8; r2++) {
                int ul = uh * 8 + r2;
                float ig = Cs[b_l * LDC + ul]      + bias_s[ul];
                float fg = Cs[b_l * LDC + 16 + ul] + bias_s[16 + ul];
                float gg = Cs[b_l * LDC + 32 + ul] + bias_s[32 + ul];
                float og = Cs[b_l * LDC + 48 + ul] + bias_s[48 + ul];
                if (t == 0) {
                    ig += add0_s[ul];      fg += add0_s[16 + ul];
                    gg += add0_s[32 + ul]; og += add0_s[48 + ul];
                }
                float si = 1.f / (1.f + expf(-ig));
                float sf = 1.f / (1.f + expf(-fg));
                float so = 1.f / (1.f + expf(-og));
                float c  = sf * c_st[r2] + si * tanhf(gg);
                float h  = so * tanhf(c);
                c_st[r2] = c;
                S_st[r2] += h;
                hv[r2] = h;
            }
            float* hwp = hw + (b0 + b_l) * Hh + ui * 16 + uh * 8;
            ((float4*)hwp)[0] = make_float4(hv[0], hv[1], hv[2], hv[3]);
            ((float4*)hwp)[1] = make_float4(hv[4], hv[5], hv[6], hv[7]);
        }

        // grid barrier (monotonic counter; reset by zero_state each launch)
        __threadfence();
        __syncthreads();
        if (tid == 0) {
            atomicAdd(&g_bar, 1u);
            volatile unsigned* vb = &g_bar;
            unsigned target = (unsigned)NBLK * (unsigned)(t + 1);
            while (*vb < target) { }
            __threadfence();
        }
        __syncthreads();
    }

    // write S once at the end
    {
        float* Sp = d_S + (b0 + b_l) * Hh + ui * 16 + uh * 8;
        ((float4*)Sp)[0] = make_float4(S_st[0], S_st[1], S_st[2], S_st[3]);
        ((float4*)Sp)[1] = make_float4(S_st[4], S_st[5], S_st[6], S_st[7]);
    }
}

// ---------------- final output: mean over t, linear in S ----------------
__global__ void final_out_kernel(float* __restrict__ out, const float* __restrict__ fc_b) {
    int idx = blockIdx.x * blockDim.x + threadIdx.x;   // 2048 outputs
    if (idx >= Bsz * 2) return;
    int b = idx >> 1, o = idx & 1;
    const float* Sb = d_S + b * Hh;
    const float* f0 = d_f0 + o * Hh;
    float s = 0.f;
#pragma unroll 8
    for (int w = 0; w < Hh; w++) s += Sb[w] * f0[w];
#pragma unroll
    for (int j = 0; j < 4; j++) {
        int bs = (4 * b + j) & (Bsz - 1);
        const float* Sp = d_S + bs * Hh;
        const float* gp = d_gv + o * 512 + j * Hh;
#pragma unroll 8
        for (int w = 0; w < Hh; w++) s += Sp[w] * gp[w];
    }
    out[idx] = s * (1.f / (float)Tt) + fc_b[o];
}

// ---------------- launch ----------------
extern "C" void kernel_launch(void* const* d_in, const int* in_sizes, int n_in,
                              void* d_out, int out_size) {
    const float* x      = (const float*)d_in[0];
    const float* memory = (const float*)d_in[1];
    const float* rv0    = (const float*)d_in[2];
    const float* W_ih   = (const float*)d_in[3];
    const float* W_hh   = (const float*)d_in[4];
    const float* b_ih   = (const float*)d_in[5];
    const float* b_hh   = (const float*)d_in[6];
    const float* fc_w   = (const float*)d_in[7];
    const float* fc_b   = (const float*)d_in[8];
    float* out = (float*)d_out;

    const int smem_bytes = (4 * 64 * LDC + 128) * 4;   // 70,144 B
    cudaFuncSetAttribute(dnc_persistent,
                         cudaFuncAttributeMaxDynamicSharedMemorySize, smem_bytes);

    zero_state_kernel<<<(Bsz * Hh + 255) / 256, 256>>>();
    softmax_kernel<<<Hh, Hh>>>(memory);
    build_wct_kernel<<<(NG * KTOT + 255) / 256, 256>>>(W_ih, W_hh);
    build_misc2_kernel<<<193, 256>>>(W_ih, rv0, b_ih, b_hh, fc_w);

    dnc_persistent<<<dim3(8, 16), 128, smem_bytes>>>(x);

    final_out_kernel<<<(Bsz * 2 + 255) / 256, 256>>>(out, fc_b);
}

// round 7
// speedup vs baseline: 1.7864x; 1.7864x over previous
#include <cuda_runtime.h>
#include <cstdint>

// Problem constants
#define Bsz   1024
#define Tt    128
#define DIN   256
#define Hh    128
#define NG    512          // 4*H gates
#define KTOT  896          // DIN + H + 4*H (x | h | 4 shuffled-h via folded read)
#define NBLK  128          // persistent grid size (8 u-tiles x 16 batch-tiles)
#define BK    64
#define HCH   7            // k-chunks per warp-group (2 groups x 7 x 64 = 896)
#define LDC   68           // smem row stride: conflict-free fragment reads

// ---------------- device scratch (static, no allocations) ----------------
__device__ float d_WcT[NG * KTOT];      // [n][k] combined weight
__device__ float d_bias[NG];
__device__ float d_add0[NG];            // t==0 read-vector bias
__device__ float d_memsm[Hh * Hh];      // softmax(memory, axis=0)
__device__ float d_hA[Bsz * Hh];        // h ping-pong
__device__ float d_hB[Bsz * Hh];
__device__ float d_S[Bsz * Hh];         // sum over t of h
__device__ float d_f0[2 * Hh];          // fc_w direct-h part
__device__ float d_gv[2 * 4 * Hh];      // fc_w read part folded through mem_sm
__device__ unsigned g_bar;              // grid barrier counter

// ---------------- helpers ----------------
__device__ __forceinline__ void mma8(float* d, const float* a, float b0f, float b1f) {
    asm volatile(
        "mma.sync.aligned.m16n8k8.row.col.f32.tf32.tf32.f32 "
        "{%0,%1,%2,%3}, {%4,%5,%6,%7}, {%8,%9}, {%0,%1,%2,%3};\n"
        : "+f"(d[0]), "+f"(d[1]), "+f"(d[2]), "+f"(d[3])
        : "r"(__float_as_uint(a[0])), "r"(__float_as_uint(a[1])),
          "r"(__float_as_uint(a[2])), "r"(__float_as_uint(a[3])),
          "r"(__float_as_uint(b0f)), "r"(__float_as_uint(b1f)));
}

__device__ __forceinline__ void cp16(uint32_t dst, const float* src) {
    asm volatile("cp.async.ca.shared.global [%0], [%1], 16;\n" :: "r"(dst), "l"(src));
}
__device__ __forceinline__ void cp_commit() { asm volatile("cp.async.commit_group;\n" ::: "memory"); }
__device__ __forceinline__ void cp_wait0()  { asm volatile("cp.async.wait_group 0;\n" ::: "memory"); }
__device__ __forceinline__ void cp_wait1()  { asm volatile("cp.async.wait_group 1;\n" ::: "memory"); }

// Source pointer for Hcat[b][k0 .. k0+15]; segment boundaries at multiples of 128,
// k0 is a multiple of 16 so a 16-float run stays inside one segment.
__device__ __forceinline__ const float* a_src(const float* __restrict__ x,
                                              const float* __restrict__ hp,
                                              int b, int t, int k0) {
    int seg = k0 >> 7;                     // 0,1: x | 2: h | 3..6: shuffled h
    if (seg < 2)  return x + (b * Tt + t) * DIN + k0;
    if (seg == 2) return hp + b * Hh + (k0 - 256);
    int j  = seg - 3;
    int bb = (4 * b + j) & (Bsz - 1);
    return hp + bb * Hh + (k0 - 384 - 128 * j);
}

// ---------------- setup kernels ----------------

__global__ void softmax_kernel(const float* __restrict__ memory) {
    int w = blockIdx.x;
    int m = threadIdx.x;
    __shared__ float red[Hh];
    float v = memory[m * Hh + w];
    red[m] = v;
    __syncthreads();
    for (int s = 64; s > 0; s >>= 1) {
        if (m < s) red[m] = fmaxf(red[m], red[m + s]);
        __syncthreads();
    }
    float mx = red[0];
    __syncthreads();
    float e = expf(v - mx);
    red[m] = e;
    __syncthreads();
    for (int s = 64; s > 0; s >>= 1) {
        if (m < s) red[m] += red[m + s];
        __syncthreads();
    }
    d_memsm[m * Hh + w] = e / red[0];
}

__global__ void build_wct_kernel(const float* __restrict__ W_ih,
                                 const float* __restrict__ W_hh) {
    int idx = blockIdx.x * blockDim.x + threadIdx.x;
    if (idx >= NG * KTOT) return;
    int n = idx / KTOT, k = idx % KTOT;
    float v;
    if (k < 256) {
        v = W_ih[n * 768 + k];
    } else if (k < 384) {
        v = W_hh[n * Hh + (k - 256)];
    } else {
        int j = (k - 384) >> 7, w = (k - 384) & 127;
        const float* wr = W_ih + n * 768 + 256 + 128 * j;
        float s = 0.f;
#pragma unroll 8
        for (int m = 0; m < 128; m++) s += wr[m] * d_memsm[m * Hh + w];
        v = s;
    }
    d_WcT[idx] = v;
}

__global__ void build_misc2_kernel(const float* __restrict__ W_ih,
                                   const float* __restrict__ rv0,
                                   const float* __restrict__ b_ih,
                                   const float* __restrict__ b_hh,
                                   const float* __restrict__ fc_w) {
    int gw   = (blockIdx.x * blockDim.x + threadIdx.x) >> 5;
    int lane = threadIdx.x & 31;
    if (gw < NG) {
        const float* wr = W_ih + gw * 768 + 256;
        float s = 0.f;
        for (int k = lane; k < 512; k += 32) s += rv0[k] * wr[k];
#pragma unroll
        for (int o = 16; o > 0; o >>= 1) s += __shfl_down_sync(0xffffffffu, s, o);
        if (lane == 0) {
            d_add0[gw] = s;
            d_bias[gw] = b_ih[gw] + b_hh[gw];
        }
    } else if (gw < NG + 1024) {
        int i2 = gw - NG;                         // [o][j][w]
        int o = i2 >> 9, j = (i2 >> 7) & 3, w = i2 & 127;
        float s = 0.f;
        for (int m = lane; m < 128; m += 32)
            s += d_memsm[m * Hh + w] * fc_w[o * 640 + 128 + 128 * j + m];
#pragma unroll
        for (int o2 = 16; o2 > 0; o2 >>= 1) s += __shfl_down_sync(0xffffffffu, s, o2);
        if (lane == 0) d_gv[i2] = s;
    } else if (gw < NG + 1024 + 8) {
        int i2 = (gw - NG - 1024) * 32 + lane;    // 256 values
        d_f0[i2] = fc_w[(i2 >> 7) * 640 + (i2 & 127)];
    }
}

__global__ void zero_state_kernel() {
    int i = blockIdx.x * blockDim.x + threadIdx.x;
    if (i < Bsz * Hh) {
        d_hA[i] = 0.f;
        d_hB[i] = 0.f;
    }
    if (i == 0) g_bar = 0u;
}

// ---------------- persistent fused recurrence kernel ----------------
// Grid (8, 16) = 128 blocks, 256 threads (8 warps, 2 per SMSP).
// Block owns batches [64*by, +64) and h-units [16*bx, +16).
// K split across 2 warp-groups (4 warps each); each group computes the full
// 64x64 C tile over its k-half; halves summed through smem per step.
// c and S live in registers for the whole T loop; h ping-pongs through global.
__global__ void __launch_bounds__(256) dnc_persistent(const float* __restrict__ x) {
    extern __shared__ float sm[];
    float* As     = sm;                       // [2 buf][2 grp][64][LDC]
    float* Bs     = sm + 4 * 64 * LDC;        // [2 buf][2 grp][64][LDC]
    float* bias_s = sm + 8 * 64 * LDC;        // 64
    float* add0_s = bias_s + 64;              // 64
    float* Cs     = sm;                       // aliases As tile (buf0, grp0)

    const int tid  = threadIdx.x;
    const int warp = tid >> 5, lane = tid & 31;
    const int grp  = warp >> 2, wl = warp & 3;     // k-group, warp-in-group
    const int wm = (wl >> 1) * 32, wn = (wl & 1) * 32;
    const int g  = lane >> 2,  t4 = lane & 3;
    const int arow = tid >> 2, acol = (tid & 3) * 16;   // loader mapping
    const int ui = blockIdx.x;                // 0..7 u-tile
    const int b0 = blockIdx.y * 64;

    if (tid < 64) {
        int ng = (tid >> 4) * 128 + ui * 16 + (tid & 15);
        bias_s[tid] = d_bias[ng];
        add0_s[tid] = d_add0[ng];
    }

    // B loader: local row arow -> global gate row
    const int brow_g = (arow >> 4) * 128 + ui * 16 + (arow & 15);
    const float* wrow = d_WcT + brow_g * KTOT;

    const uint32_t dA = (uint32_t)__cvta_generic_to_shared(As + arow * LDC + acol);
    const uint32_t dB = (uint32_t)__cvta_generic_to_shared(Bs + arow * LDC + acol);
    const uint32_t tileBytes = 64 * LDC * 4;

    float c_st[4], S_st[4];
#pragma unroll
    for (int r = 0; r < 4; r++) { c_st[r] = 0.f; S_st[r] = 0.f; }

    const int b_l = tid >> 2, uq = tid & 3;   // update-phase ownership

#pragma unroll 1
    for (int t = 0; t < Tt; t++) {
        const float* hp = (t & 1) ? d_hB : d_hA;
        float*       hw = (t & 1) ? d_hA : d_hB;

        float acc[2][4][4];
#pragma unroll
        for (int i = 0; i < 2; i++)
#pragma unroll
            for (int j = 0; j < 4; j++)
#pragma unroll
                for (int q = 0; q < 4; q++) acc[i][j][q] = 0.f;

        // prologue: chunk 0 (both groups) -> buffer 0
#pragma unroll
        for (int gg = 0; gg < 2; gg++) {
            int k0 = (gg * HCH) * BK + acol;
            const float* sa = a_src(x, hp, b0 + arow, t, k0);
            uint32_t da = dA + (uint32_t)gg * tileBytes;
            cp16(da,      sa);      cp16(da + 16, sa + 4);
            cp16(da + 32, sa + 8);  cp16(da + 48, sa + 12);
            const float* sb = wrow + k0;
            uint32_t db = dB + (uint32_t)gg * tileBytes;
            cp16(db,      sb);      cp16(db + 16, sb + 4);
            cp16(db + 32, sb + 8);  cp16(db + 48, sb + 12);
        }
        cp_commit();

#pragma unroll 1
        for (int ck = 0; ck < HCH; ck++) {
            int cur = ck & 1;
            if (ck < HCH - 1) {
                int nb = cur ^ 1;
#pragma unroll
                for (int gg = 0; gg < 2; gg++) {
                    int k0 = (gg * HCH + ck + 1) * BK + acol;
                    const float* sa = a_src(x, hp, b0 + arow, t, k0);
                    uint32_t da = dA + (uint32_t)(nb * 2 + gg) * tileBytes;
                    cp16(da,      sa);      cp16(da + 16, sa + 4);
                    cp16(da + 32, sa + 8);  cp16(da + 48, sa + 12);
                    const float* sb = wrow + k0;
                    uint32_t db = dB + (uint32_t)(nb * 2 + gg) * tileBytes;
                    cp16(db,      sb);      cp16(db + 16, sb + 4);
                    cp16(db + 32, sb + 8);  cp16(db + 48, sb + 12);
                }
                cp_commit();
                cp_wait1();
            } else {
                cp_wait0();
            }
            __syncthreads();

            const float* Ac = As + (cur * 2 + grp) * 64 * LDC;
            const float* Bc = Bs + (cur * 2 + grp) * 64 * LDC;
#pragma unroll
            for (int ks = 0; ks < 8; ks++) {
                float afr[2][4];
#pragma unroll
                for (int mi = 0; mi < 2; mi++) {
                    int mr = wm + mi * 16;
                    afr[mi][0] = Ac[(mr + g) * LDC + ks * 8 + t4];
                    afr[mi][1] = Ac[(mr + g + 8) * LDC + ks * 8 + t4];
                    afr[mi][2] = Ac[(mr + g) * LDC + ks * 8 + t4 + 4];
                    afr[mi][3] = Ac[(mr + g + 8) * LDC + ks * 8 + t4 + 4];
                }
#pragma unroll
                for (int ni = 0; ni < 4; ni++) {
                    int nr = wn + ni * 8;
                    float bf0 = Bc[(nr + g) * LDC + ks * 8 + t4];
                    float bf1 = Bc[(nr + g) * LDC + ks * 8 + t4 + 4];
                    mma8(acc[0][ni], afr[0], bf0, bf1);
                    mma8(acc[1][ni], afr[1], bf0, bf1);
                }
            }
            __syncthreads();
        }

        // cross-group reduction through Cs (aliases As buf0/grp0; safe after sync)
        if (grp == 1) {
#pragma unroll
            for (int mi = 0; mi < 2; mi++)
#pragma unroll
                for (int ni = 0; ni < 4; ni++) {
                    int r = wm + mi * 16 + g, cidx = wn + ni * 8 + 2 * t4;
                    Cs[r * LDC + cidx]           = acc[mi][ni][0];
                    Cs[r * LDC + cidx + 1]       = acc[mi][ni][1];
                    Cs[(r + 8) * LDC + cidx]     = acc[mi][ni][2];
                    Cs[(r + 8) * LDC + cidx + 1] = acc[mi][ni][3];
                }
        }
        __syncthreads();
        if (grp == 0) {
#pragma unroll
            for (int mi = 0; mi < 2; mi++)
#pragma unroll
                for (int ni = 0; ni < 4; ni++) {
                    int r = wm + mi * 16 + g, cidx = wn + ni * 8 + 2 * t4;
                    Cs[r * LDC + cidx]           += acc[mi][ni][0];
                    Cs[r * LDC + cidx + 1]       += acc[mi][ni][1];
                    Cs[(r + 8) * LDC + cidx]     += acc[mi][ni][2];
                    Cs[(r + 8) * LDC + cidx + 1] += acc[mi][ni][3];
                }
        }
        __syncthreads();

        // fused LSTM update: thread owns (b_l, 4 u's); c/S in registers
        {
            float hv[4];
#pragma unroll
            for (int r2 = 0; r2 < 4; r2++) {
                int ul = uq * 4 + r2;
                float ig  = Cs[b_l * LDC + ul]      + bias_s[ul];
                float fg  = Cs[b_l * LDC + 16 + ul] + bias_s[16 + ul];
                float gg2 = Cs[b_l * LDC + 32 + ul] + bias_s[32 + ul];
                float og  = Cs[b_l * LDC + 48 + ul] + bias_s[48 + ul];
                if (t == 0) {
                    ig  += add0_s[ul];      fg += add0_s[16 + ul];
                    gg2 += add0_s[32 + ul]; og += add0_s[48 + ul];
                }
                float si = 1.f / (1.f + expf(-ig));
                float sf = 1.f / (1.f + expf(-fg));
                float so = 1.f / (1.f + expf(-og));
                float c  = sf * c_st[r2] + si * tanhf(gg2);
                float h  = so * tanhf(c);
                c_st[r2] = c;
                S_st[r2] += h;
                hv[r2] = h;
            }
            float* hwp = hw + (b0 + b_l) * Hh + ui * 16 + uq * 4;
            *(float4*)hwp = make_float4(hv[0], hv[1], hv[2], hv[3]);
        }

        // grid barrier (monotonic counter; reset by zero_state each launch).
        // Writer-side threadfence publishes h; reader-side threadfence emits
        // CCTL.IVALL, invalidating this SM's L1 before next step's loads.
        __threadfence();
        __syncthreads();
        if (tid == 0) {
            atomicAdd(&g_bar, 1u);
            volatile unsigned* vb = &g_bar;
            unsigned target = (unsigned)NBLK * (unsigned)(t + 1);
            while (*vb < target) { }
            __threadfence();
        }
        __syncthreads();
    }

    // write S once at the end
    {
        float* Sp = d_S + (b0 + b_l) * Hh + ui * 16 + uq * 4;
        *(float4*)Sp = make_float4(S_st[0], S_st[1], S_st[2], S_st[3]);
    }
}

// ---------------- final output: mean over t, linear in S ----------------
__global__ void final_out_kernel(float* __restrict__ out, const float* __restrict__ fc_b) {
    int idx = blockIdx.x * blockDim.x + threadIdx.x;   // 2048 outputs
    if (idx >= Bsz * 2) return;
    int b = idx >> 1, o = idx & 1;
    const float* Sb = d_S + b * Hh;
    const float* f0 = d_f0 + o * Hh;
    float s = 0.f;
#pragma unroll 8
    for (int w = 0; w < Hh; w++) s += Sb[w] * f0[w];
#pragma unroll
    for (int j = 0; j < 4; j++) {
        int bs = (4 * b + j) & (Bsz - 1);
        const float* Sp = d_S + bs * Hh;
        const float* gp = d_gv + o * 512 + j * Hh;
#pragma unroll 8
        for (int w = 0; w < Hh; w++) s += Sp[w] * gp[w];
    }
    out[idx] = s * (1.f / (float)Tt) + fc_b[o];
}

// ---------------- launch ----------------
extern "C" void kernel_launch(void* const* d_in, const int* in_sizes, int n_in,
                              void* d_out, int out_size) {
    const float* x      = (const float*)d_in[0];
    const float* memory = (const float*)d_in[1];
    const float* rv0    = (const float*)d_in[2];
    const float* W_ih   = (const float*)d_in[3];
    const float* W_hh   = (const float*)d_in[4];
    const float* b_ih   = (const float*)d_in[5];
    const float* b_hh   = (const float*)d_in[6];
    const float* fc_w   = (const float*)d_in[7];
    const float* fc_b   = (const float*)d_in[8];
    float* out = (float*)d_out;

    const int smem_bytes = (8 * 64 * LDC + 128) * 4;   // 139,776 B
    cudaFuncSetAttribute(dnc_persistent,
                         cudaFuncAttributeMaxDynamicSharedMemorySize, smem_bytes);

    zero_state_kernel<<<(Bsz * Hh + 255) / 256, 256>>>();
    softmax_kernel<<<Hh, Hh>>>(memory);
    build_wct_kernel<<<(NG * KTOT + 255) / 256, 256>>>(W_ih, W_hh);
    build_misc2_kernel<<<193, 256>>>(W_ih, rv0, b_ih, b_hh, fc_w);

    dnc_persistent<<<dim3(8, 16), 256, smem_bytes>>>(x);

    final_out_kernel<<<(Bsz * 2 + 255) / 256, 256>>>(out, fc_b);
}

// round 9
// speedup vs baseline: 2.0895x; 1.1696x over previous
#include <cuda_runtime.h>
#include <cstdint>

// Problem constants
#define Bsz   1024
#define Tt    128
#define DIN   256
#define Hh    128
#define NG    512          // 4*H gates
#define KW    640          // recurrent K: h(128) + hq(512)
#define KG    320          // K per warp-group
#define NCH   10           // BK=32 chunk indices per step
#define NBLK  128          // persistent grid (8 u-tiles x 16 batch-tiles)
#define LDA   36
#define LDB   324
#define LDCc  68

// ---------------- device scratch (static, no allocations) ----------------
__device__ float d_WcT[NG * KW];        // [n][k'] folded recurrent weight (Whh | Acat)
__device__ float d_bias[NG];
__device__ float d_add0[NG];            // t==0 read-vector bias
__device__ float d_memsm[Hh * Hh];      // softmax(memory, axis=0)
__device__ float d_hA[Bsz * Hh];        // h ping-pong
__device__ float d_hB[Bsz * Hh];
__device__ float d_S[Bsz * Hh];         // sum over t of h
__device__ float d_f0[2 * Hh];
__device__ float d_gv[2 * 4 * Hh];
__device__ float d_gx[(size_t)Tt * Bsz * NG];   // precomputed x@Wx^T, [t][b][n] (256MB)
__device__ unsigned g_bar;              // grid barrier counter

// ---------------- helpers ----------------
__device__ __forceinline__ void mma8(float* d, const float* a, float b0f, float b1f) {
    asm volatile(
        "mma.sync.aligned.m16n8k8.row.col.f32.tf32.tf32.f32 "
        "{%0,%1,%2,%3}, {%4,%5,%6,%7}, {%8,%9}, {%0,%1,%2,%3};\n"
        : "+f"(d[0]), "+f"(d[1]), "+f"(d[2]), "+f"(d[3])
        : "r"(__float_as_uint(a[0])), "r"(__float_as_uint(a[1])),
          "r"(__float_as_uint(a[2])), "r"(__float_as_uint(a[3])),
          "r"(__float_as_uint(b0f)), "r"(__float_as_uint(b1f)));
}

__device__ __forceinline__ void cp16(uint32_t dst, const float* src) {
    asm volatile("cp.async.cg.shared.global [%0], [%1], 16;\n" :: "r"(dst), "l"(src));
}
__device__ __forceinline__ void cp_commit() { asm volatile("cp.async.commit_group;\n" ::: "memory"); }
__device__ __forceinline__ void cp_wait0()  { asm volatile("cp.async.wait_group 0;\n" ::: "memory"); }
__device__ __forceinline__ void cp_wait1()  { asm volatile("cp.async.wait_group 1;\n" ::: "memory"); }

// ---------------- setup kernels ----------------

__global__ void softmax_kernel(const float* __restrict__ memory) {
    int w = blockIdx.x;
    int m = threadIdx.x;
    __shared__ float red[Hh];
    float v = memory[m * Hh + w];
    red[m] = v;
    __syncthreads();
    for (int s = 64; s > 0; s >>= 1) {
        if (m < s) red[m] = fmaxf(red[m], red[m + s]);
        __syncthreads();
    }
    float mx = red[0];
    __syncthreads();
    float e = expf(v - mx);
    red[m] = e;
    __syncthreads();
    for (int s = 64; s > 0; s >>= 1) {
        if (m < s) red[m] += red[m + s];
        __syncthreads();
    }
    d_memsm[m * Hh + w] = e / red[0];
}

// WcT[n][k'] : k'<128 -> W_hh[n,k'] ; else Acat[n, k'-128] with
// Acat[n, 128j+w] = sum_m W_ih[n, 256+128j+m] * memsm[m, w]
__global__ void build_wct2_kernel(const float* __restrict__ W_ih,
                                  const float* __restrict__ W_hh) {
    int idx = blockIdx.x * blockDim.x + threadIdx.x;
    if (idx >= NG * KW) return;
    int n = idx / KW, k = idx % KW;
    float v;
    if (k < 128) {
        v = W_hh[n * Hh + k];
    } else {
        int j = (k - 128) >> 7, w = (k - 128) & 127;
        const float* wr = W_ih + n * 768 + 256 + 128 * j;
        float s = 0.f;
#pragma unroll 8
        for (int m = 0; m < 128; m++) s += wr[m] * d_memsm[m * Hh + w];
        v = s;
    }
    d_WcT[idx] = v;
}

__global__ void build_misc2_kernel(const float* __restrict__ W_ih,
                                   const float* __restrict__ rv0,
                                   const float* __restrict__ b_ih,
                                   const float* __restrict__ b_hh,
                                   const float* __restrict__ fc_w) {
    int gw   = (blockIdx.x * blockDim.x + threadIdx.x) >> 5;
    int lane = threadIdx.x & 31;
    if (gw < NG) {
        const float* wr = W_ih + gw * 768 + 256;
        float s = 0.f;
        for (int k = lane; k < 512; k += 32) s += rv0[k] * wr[k];
#pragma unroll
        for (int o = 16; o > 0; o >>= 1) s += __shfl_down_sync(0xffffffffu, s, o);
        if (lane == 0) {
            d_add0[gw] = s;
            d_bias[gw] = b_ih[gw] + b_hh[gw];
        }
    } else if (gw < NG + 1024) {
        int i2 = gw - NG;                         // [o][j][w]
        int o = i2 >> 9, j = (i2 >> 7) & 3, w = i2 & 127;
        float s = 0.f;
        for (int m = lane; m < 128; m += 32)
            s += d_memsm[m * Hh + w] * fc_w[o * 640 + 128 + 128 * j + m];
#pragma unroll
        for (int o2 = 16; o2 > 0; o2 >>= 1) s += __shfl_down_sync(0xffffffffu, s, o2);
        if (lane == 0) d_gv[i2] = s;
    } else if (gw < NG + 1024 + 8) {
        int i2 = (gw - NG - 1024) * 32 + lane;
        d_f0[i2] = fc_w[(i2 >> 7) * 640 + (i2 & 127)];
    }
}

__global__ void zero_state_kernel() {
    int i = blockIdx.x * blockDim.x + threadIdx.x;
    if (i < Bsz * Hh) {
        d_hA[i] = 0.f;
        d_hB[i] = 0.f;
    }
    if (i == 0) g_bar = 0u;
}

// ---------------- gx pre-pass: d_gx[t][b][n] = x[b][t] @ W_ih[:, :256]^T ----------------
// 64x64 C tile, 256 threads, K=256 split across 2 warp-groups (128 each, BK=64).
__global__ void __launch_bounds__(256) gx_kernel(const float* __restrict__ x,
                                                 const float* __restrict__ W_ih) {
    extern __shared__ float sm[];
    float* As = sm;                       // [2 buf][2 grp][64][68]
    float* Bs = sm + 4 * 64 * LDCc;
    float* Cs = sm;                       // alias buf0/grp0

    const int tid  = threadIdx.x;
    const int warp = tid >> 5, lane = tid & 31;
    const int grp  = warp >> 2, wl = warp & 3;
    const int wm = (wl >> 1) * 32, wn = (wl & 1) * 32;
    const int g  = lane >> 2,  t4 = lane & 3;
    const int arow = tid >> 2, acol = (tid & 3) * 16;
    const int n0 = blockIdx.x * 64;
    const int r0 = blockIdx.y * 64;       // row in [0, 131072)

    const float* xr = x + (size_t)(r0 + arow) * DIN + acol;
    const float* wr = W_ih + (size_t)(n0 + arow) * 768 + acol;
    const uint32_t dA = (uint32_t)__cvta_generic_to_shared(As + arow * LDCc + acol);
    const uint32_t dB = (uint32_t)__cvta_generic_to_shared(Bs + arow * LDCc + acol);
    const uint32_t tileBytes = 64 * LDCc * 4;

    float acc[2][4][4];
#pragma unroll
    for (int i = 0; i < 2; i++)
#pragma unroll
        for (int j = 0; j < 4; j++)
#pragma unroll
            for (int q = 0; q < 4; q++) acc[i][j][q] = 0.f;

    // prologue: chunk 0 of both groups -> buf 0
#pragma unroll
    for (int gg = 0; gg < 2; gg++) {
        int k0 = gg * 128;
        uint32_t da = dA + (uint32_t)gg * tileBytes;
        cp16(da,      xr + k0);      cp16(da + 16, xr + k0 + 4);
        cp16(da + 32, xr + k0 + 8);  cp16(da + 48, xr + k0 + 12);
        uint32_t db = dB + (uint32_t)gg * tileBytes;
        cp16(db,      wr + k0);      cp16(db + 16, wr + k0 + 4);
        cp16(db + 32, wr + k0 + 8);  cp16(db + 48, wr + k0 + 12);
    }
    cp_commit();

#pragma unroll
    for (int ck = 0; ck < 2; ck++) {
        int cur = ck & 1;
        if (ck == 0) {
#pragma unroll
            for (int gg = 0; gg < 2; gg++) {
                int k0 = gg * 128 + 64;
                uint32_t da = dA + (uint32_t)(2 + gg) * tileBytes;
                cp16(da,      xr + k0);      cp16(da + 16, xr + k0 + 4);
                cp16(da + 32, xr + k0 + 8);  cp16(da + 48, xr + k0 + 12);
                uint32_t db = dB + (uint32_t)(2 + gg) * tileBytes;
                cp16(db,      wr + k0);      cp16(db + 16, wr + k0 + 4);
                cp16(db + 32, wr + k0 + 8);  cp16(db + 48, wr + k0 + 12);
            }
            cp_commit();
            cp_wait1();
        } else {
            cp_wait0();
        }
        __syncthreads();
        const float* Ac = As + (cur * 2 + grp) * 64 * LDCc;
        const float* Bc = Bs + (cur * 2 + grp) * 64 * LDCc;
#pragma unroll
        for (int ks = 0; ks < 8; ks++) {
            float afr[2][4];
#pragma unroll
            for (int mi = 0; mi < 2; mi++) {
                int mr = wm + mi * 16;
                afr[mi][0] = Ac[(mr + g) * LDCc + ks * 8 + t4];
                afr[mi][1] = Ac[(mr + g + 8) * LDCc + ks * 8 + t4];
                afr[mi][2] = Ac[(mr + g) * LDCc + ks * 8 + t4 + 4];
                afr[mi][3] = Ac[(mr + g + 8) * LDCc + ks * 8 + t4 + 4];
            }
#pragma unroll
            for (int ni = 0; ni < 4; ni++) {
                int nr = wn + ni * 8;
                float bf0 = Bc[(nr + g) * LDCc + ks * 8 + t4];
                float bf1 = Bc[(nr + g) * LDCc + ks * 8 + t4 + 4];
                mma8(acc[0][ni], afr[0], bf0, bf1);
                mma8(acc[1][ni], afr[1], bf0, bf1);
            }
        }
        __syncthreads();
    }

    // reduce across groups through Cs, then write to d_gx with [t][b][n] permute
    if (grp == 1) {
#pragma unroll
        for (int mi = 0; mi < 2; mi++)
#pragma unroll
            for (int ni = 0; ni < 4; ni++) {
                int r = wm + mi * 16 + g, cidx = wn + ni * 8 + 2 * t4;
                Cs[r * LDCc + cidx]           = acc[mi][ni][0];
                Cs[r * LDCc + cidx + 1]       = acc[mi][ni][1];
                Cs[(r + 8) * LDCc + cidx]     = acc[mi][ni][2];
                Cs[(r + 8) * LDCc + cidx + 1] = acc[mi][ni][3];
            }
    }
    __syncthreads();
    if (grp == 0) {
#pragma unroll
        for (int mi = 0; mi < 2; mi++)
#pragma unroll
            for (int ni = 0; ni < 4; ni++) {
                int r = wm + mi * 16 + g, cidx = wn + ni * 8 + 2 * t4;
                Cs[r * LDCc + cidx]           += acc[mi][ni][0];
                Cs[r * LDCc + cidx + 1]       += acc[mi][ni][1];
                Cs[(r + 8) * LDCc + cidx]     += acc[mi][ni][2];
                Cs[(r + 8) * LDCc + cidx + 1] += acc[mi][ni][3];
            }
    }
    __syncthreads();

    {
        int row = tid >> 2, col4 = (tid & 3) * 16;
        int r = r0 + row;
        int b = r >> 7, tt = r & 127;
        float* dst = d_gx + ((size_t)tt * Bsz + b) * NG + n0 + col4;
#pragma unroll
        for (int i = 0; i < 4; i++) {
            float* s = Cs + row * LDCc + col4 + 4 * i;
            ((float4*)dst)[i] = make_float4(s[0], s[1], s[2], s[3]);
        }
    }
}

// ---------------- persistent fused recurrence kernel ----------------
// Grid (8, 16), 256 threads. C tile: 64 batches x 64 gate-cols (4 gates x 16 u's).
// A per step = [h[b] (128) | hq[b%256] (512)] streamed BK=32 via 3-stage cp.async ring.
// B (64x640) resident in smem for all 128 steps. gx tile prefetched to regs.
__global__ void __launch_bounds__(256) dnc_persistent() {
    extern __shared__ float sm[];
    float* Amem   = sm;                     // [3 stage][2 grp][64*36] = 13824 floats
    float* Bres   = sm + 13824;             // [2 grp][64*324] = 41472 floats
    float* bias_s = sm + 13824 + 41472;     // 64
    float* add0_s = bias_s + 64;            // 64
    float* Cs     = sm;                     // alias stage0 region (needs 64*68=4352)

    const int tid  = threadIdx.x;
    const int warp = tid >> 5, lane = tid & 31;
    const int grp  = warp >> 2, wl = warp & 3;
    const int wm = (wl >> 1) * 32, wn = (wl & 1) * 32;
    const int g  = lane >> 2,  t4 = lane & 3;
    const int arow = tid >> 2, acol8 = (tid & 3) * 8;
    const int ui = blockIdx.x;
    const int b0 = blockIdx.y * 64;

    if (tid < 64) {
        int ng = (tid >> 4) * 128 + ui * 16 + (tid & 15);
        bias_s[tid] = d_bias[ng];
        add0_s[tid] = d_add0[ng];
    }
    // resident B: local row rr -> gate (rr>>4)*128 + ui*16 + (rr&15), k' in [grp*320, +320)
    for (int i = tid * 4; i < 2 * 64 * 320; i += 1024) {
        int gg  = i / 20480;
        int rem = i - gg * 20480;
        int row = rem / 320, col = rem - row * 320;
        int n   = (row >> 4) * 128 + ui * 16 + (row & 15);
        float4 v = *(const float4*)(d_WcT + n * KW + gg * 320 + col);
        *(float4*)(Bres + gg * (64 * LDB) + row * LDB + col) = v;
    }
    __syncthreads();

    const uint32_t aBase = (uint32_t)__cvta_generic_to_shared(Amem) +
                           (uint32_t)((arow * LDA + acol8) * 4);
    const int bglob = b0 + arow;            // A-loader's batch row
    const int bq    = bglob & 255;          // hq row

    float c_st[4], S_st[4];
#pragma unroll
    for (int r = 0; r < 4; r++) { c_st[r] = 0.f; S_st[r] = 0.f; }

    const int b_l = tid >> 2, uq = tid & 3; // update-phase ownership

#pragma unroll 1
    for (int t = 0; t < Tt; t++) {
        const float* hp = (t & 1) ? d_hB : d_hA;
        float*       hw = (t & 1) ? d_hA : d_hB;

        // gx prefetch (independent of h; hidden by chunk loop)
        const float* gxp = d_gx + ((size_t)t * Bsz + b0 + b_l) * NG + ui * 16 + uq * 4;
        float4 gx0 = ((const float4*)(gxp))[0];
        float4 gx1 = ((const float4*)(gxp + 128))[0];
        float4 gx2 = ((const float4*)(gxp + 256))[0];
        float4 gx3 = ((const float4*)(gxp + 384))[0];

        float acc[2][4][4];
#pragma unroll
        for (int i = 0; i < 2; i++)
#pragma unroll
            for (int j = 0; j < 4; j++)
#pragma unroll
                for (int q = 0; q < 4; q++) acc[i][j][q] = 0.f;

        auto issueA = [&](int ci, int st) {
#pragma unroll
            for (int gg = 0; gg < 2; gg++) {
                int k0 = gg * KG + ci * 32;
                const float* src = (k0 < 128)
                    ? hp + bglob * Hh + k0 + acol8
                    : hp + bq * 512 + (k0 - 128) + acol8;
                uint32_t dst = aBase + (uint32_t)((st * 2 + gg) * (64 * LDA) * 4);
                cp16(dst, src);
                cp16(dst + 16, src + 4);
            }
        };

        issueA(0, 0); cp_commit();
        issueA(1, 1); cp_commit();

#pragma unroll 1
        for (int ck = 0; ck < NCH; ck++) {
            if (ck < NCH - 1) cp_wait1(); else cp_wait0();
            __syncthreads();
            if (ck + 2 < NCH) { issueA(ck + 2, (ck + 2) % 3); cp_commit(); }

            const float* Ac = Amem + ((ck % 3) * 2 + grp) * (64 * LDA);
            const float* Bc = Bres + grp * (64 * LDB);
            const int cb = ck * 32;
#pragma unroll
            for (int ks = 0; ks < 4; ks++) {
                float afr[2][4];
#pragma unroll
                for (int mi = 0; mi < 2; mi++) {
                    int mr = wm + mi * 16;
                    afr[mi][0] = Ac[(mr + g) * LDA + ks * 8 + t4];
                    afr[mi][1] = Ac[(mr + g + 8) * LDA + ks * 8 + t4];
                    afr[mi][2] = Ac[(mr + g) * LDA + ks * 8 + t4 + 4];
                    afr[mi][3] = Ac[(mr + g + 8) * LDA + ks * 8 + t4 + 4];
                }
#pragma unroll
                for (int ni = 0; ni < 4; ni++) {
                    int nr = wn + ni * 8;
                    float bf0 = Bc[(nr + g) * LDB + cb + ks * 8 + t4];
                    float bf1 = Bc[(nr + g) * LDB + cb + ks * 8 + t4 + 4];
                    mma8(acc[0][ni], afr[0], bf0, bf1);
                    mma8(acc[1][ni], afr[1], bf0, bf1);
                }
            }
        }
        __syncthreads();

        // cross-group reduction through Cs (aliases A stage0; safe after sync)
        if (grp == 1) {
#pragma unroll
            for (int mi = 0; mi < 2; mi++)
#pragma unroll
                for (int ni = 0; ni < 4; ni++) {
                    int r = wm + mi * 16 + g, cidx = wn + ni * 8 + 2 * t4;
                    Cs[r * LDCc + cidx]           = acc[mi][ni][0];
                    Cs[r * LDCc + cidx + 1]       = acc[mi][ni][1];
                    Cs[(r + 8) * LDCc + cidx]     = acc[mi][ni][2];
                    Cs[(r + 8) * LDCc + cidx + 1] = acc[mi][ni][3];
                }
        }
        __syncthreads();
        if (grp == 0) {
#pragma unroll
            for (int mi = 0; mi < 2; mi++)
#pragma unroll
                for (int ni = 0; ni < 4; ni++) {
                    int r = wm + mi * 16 + g, cidx = wn + ni * 8 + 2 * t4;
                    Cs[r * LDCc + cidx]           += acc[mi][ni][0];
                    Cs[r * LDCc + cidx + 1]       += acc[mi][ni][1];
                    Cs[(r + 8) * LDCc + cidx]     += acc[mi][ni][2];
                    Cs[(r + 8) * LDCc + cidx + 1] += acc[mi][ni][3];
                }
        }
        __syncthreads();

        // fused LSTM update: thread owns (b_l, 4 u's); c/S in registers
        {
            const float* gxa[4] = { (const float*)&gx0, (const float*)&gx1,
                                    (const float*)&gx2, (const float*)&gx3 };
            float hv[4];
#pragma unroll
            for (int r2 = 0; r2 < 4; r2++) {
                int ul = uq * 4 + r2;
                float ig  = Cs[b_l * LDCc + ul]      + bias_s[ul]      + gxa[0][r2];
                float fg  = Cs[b_l * LDCc + 16 + ul] + bias_s[16 + ul] + gxa[1][r2];
                float gg2 = Cs[b_l * LDCc + 32 + ul] + bias_s[32 + ul] + gxa[2][r2];
                float og  = Cs[b_l * LDCc + 48 + ul] + bias_s[48 + ul] + gxa[3][r2];
                if (t == 0) {
                    ig  += add0_s[ul];      fg += add0_s[16 + ul];
                    gg2 += add0_s[32 + ul]; og += add0_s[48 + ul];
                }
                float si = 1.f / (1.f + expf(-ig));
                float sf = 1.f / (1.f + expf(-fg));
                float so = 1.f / (1.f + expf(-og));
                float c  = sf * c_st[r2] + si * tanhf(gg2);
                float h  = so * tanhf(c);
                c_st[r2] = c;
                S_st[r2] += h;
                hv[r2] = h;
            }
            float* hwp = hw + (b0 + b_l) * Hh + ui * 16 + uq * 4;
            *(float4*)hwp = make_float4(hv[0], hv[1], hv[2], hv[3]);
        }

        // grid barrier (monotonic counter, reset each launch)
        __threadfence();
        __syncthreads();
        if (tid == 0) {
            atomicAdd(&g_bar, 1u);
            volatile unsigned* vb = &g_bar;
            unsigned target = (unsigned)NBLK * (unsigned)(t + 1);
            while (*vb < target) { }
            __threadfence();
        }
        __syncthreads();
    }

    {
        float* Sp = d_S + (b0 + b_l) * Hh + ui * 16 + uq * 4;
        *(float4*)Sp = make_float4(S_st[0], S_st[1], S_st[2], S_st[3]);
    }
}

// ---------------- final output: mean over t, linear in S ----------------
__global__ void final_out_kernel(float* __restrict__ out, const float* __restrict__ fc_b) {
    int idx = blockIdx.x * blockDim.x + threadIdx.x;
    if (idx >= Bsz * 2) return;
    int b = idx >> 1, o = idx & 1;
    const float* Sb = d_S + b * Hh;
    const float* f0 = d_f0 + o * Hh;
    float s = 0.f;
#pragma unroll 8
    for (int w = 0; w < Hh; w++) s += Sb[w] * f0[w];
#pragma unroll
    for (int j = 0; j < 4; j++) {
        int bs = (4 * b + j) & (Bsz - 1);
        const float* Sp = d_S + bs * Hh;
        const float* gp = d_gv + o * 512 + j * Hh;
#pragma unroll 8
        for (int w = 0; w < Hh; w++) s += Sp[w] * gp[w];
    }
    out[idx] = s * (1.f / (float)Tt) + fc_b[o];
}

// ---------------- launch ----------------
extern "C" void kernel_launch(void* const* d_in, const int* in_sizes, int n_in,
                              void* d_out, int out_size) {
    const float* x      = (const float*)d_in[0];
    const float* memory = (const float*)d_in[1];
    const float* rv0    = (const float*)d_in[2];
    const float* W_ih   = (const float*)d_in[3];
    const float* W_hh   = (const float*)d_in[4];
    const float* b_ih   = (const float*)d_in[5];
    const float* b_hh   = (const float*)d_in[6];
    const float* fc_w   = (const float*)d_in[7];
    const float* fc_b   = (const float*)d_in[8];
    float* out = (float*)d_out;

    const int smem_pers = (13824 + 41472 + 128) * 4;     // 221,696 B
    const int smem_gx   = (8 * 64 * LDCc) * 4;           // 139,264 B
    cudaFuncSetAttribute(dnc_persistent,
                         cudaFuncAttributeMaxDynamicSharedMemorySize, smem_pers);
    cudaFuncSetAttribute(gx_kernel,
                         cudaFuncAttributeMaxDynamicSharedMemorySize, smem_gx);

    zero_state_kernel<<<(Bsz * Hh + 255) / 256, 256>>>();
    softmax_kernel<<<Hh, Hh>>>(memory);
    build_wct2_kernel<<<(NG * KW + 255) / 256, 256>>>(W_ih, W_hh);
    build_misc2_kernel<<<193, 256>>>(W_ih, rv0, b_ih, b_hh, fc_w);

    gx_kernel<<<dim3(8, (Bsz * Tt) / 64), 256, smem_gx>>>(x, W_ih);

    dnc_persistent<<<dim3(8, 16), 256, smem_pers>>>();

    final_out_kernel<<<(Bsz * 2 + 255) / 256, 256>>>(out, fc_b);
}

// round 10
// speedup vs baseline: 2.3366x; 1.1182x over previous
#include <cuda_runtime.h>
#include <cstdint>

// Problem constants
#define Bsz   1024
#define Tt    128
#define DIN   256
#define Hh    128
#define NG    512          // 4*H gates
#define KW    640          // recurrent K: h(128) + hq(512)
#define NBLK  128          // persistent grid (8 u-tiles x 16 batch-group-tiles)
#define LDA1  36
#define LDA2  68
#define LDB   644
#define LDCc  68

// ---------------- device scratch (static, no allocations) ----------------
__device__ float d_WcT[NG * KW];        // [n][k'] folded recurrent weight (Whh | Acat)
__device__ float d_bias[NG];
__device__ float d_add0[NG];            // t==0 read-vector bias
__device__ float d_memsm[Hh * Hh];      // softmax(memory, axis=0)
__device__ float d_hA[Bsz * Hh];        // h ping-pong
__device__ float d_hB[Bsz * Hh];
__device__ float d_S[Bsz * Hh];         // sum over t of h
__device__ float d_f0[2 * Hh];
__device__ float d_gv[2 * 4 * Hh];
__device__ float d_gx[(size_t)Tt * Bsz * NG];   // precomputed x@Wx^T, [t][b][n]
__device__ unsigned g_bar;              // grid barrier counter

// ---------------- helpers ----------------
__device__ __forceinline__ void mma8(float* d, const float* a, float b0f, float b1f) {
    asm volatile(
        "mma.sync.aligned.m16n8k8.row.col.f32.tf32.tf32.f32 "
        "{%0,%1,%2,%3}, {%4,%5,%6,%7}, {%8,%9}, {%0,%1,%2,%3};\n"
        : "+f"(d[0]), "+f"(d[1]), "+f"(d[2]), "+f"(d[3])
        : "r"(__float_as_uint(a[0])), "r"(__float_as_uint(a[1])),
          "r"(__float_as_uint(a[2])), "r"(__float_as_uint(a[3])),
          "r"(__float_as_uint(b0f)), "r"(__float_as_uint(b1f)));
}

__device__ __forceinline__ void cp16(uint32_t dst, const float* src) {
    asm volatile("cp.async.cg.shared.global [%0], [%1], 16;\n" :: "r"(dst), "l"(src));
}
__device__ __forceinline__ void cp_commit() { asm volatile("cp.async.commit_group;\n" ::: "memory"); }
__device__ __forceinline__ void cp_wait0()  { asm volatile("cp.async.wait_group 0;\n" ::: "memory"); }
__device__ __forceinline__ void cp_wait1()  { asm volatile("cp.async.wait_group 1;\n" ::: "memory"); }

// ---------------- setup kernels ----------------

__global__ void softmax_kernel(const float* __restrict__ memory) {
    int w = blockIdx.x;
    int m = threadIdx.x;
    __shared__ float red[Hh];
    float v = memory[m * Hh + w];
    red[m] = v;
    __syncthreads();
    for (int s = 64; s > 0; s >>= 1) {
        if (m < s) red[m] = fmaxf(red[m], red[m + s]);
        __syncthreads();
    }
    float mx = red[0];
    __syncthreads();
    float e = expf(v - mx);
    red[m] = e;
    __syncthreads();
    for (int s = 64; s > 0; s >>= 1) {
        if (m < s) red[m] += red[m + s];
        __syncthreads();
    }
    d_memsm[m * Hh + w] = e / red[0];
}

// WcT[n][k'] : k'<128 -> W_hh[n,k'] ; else Acat[n, k'-128] with
// Acat[n, 128j+w] = sum_m W_ih[n, 256+128j+m] * memsm[m, w]
__global__ void build_wct2_kernel(const float* __restrict__ W_ih,
                                  const float* __restrict__ W_hh) {
    int idx = blockIdx.x * blockDim.x + threadIdx.x;
    if (idx >= NG * KW) return;
    int n = idx / KW, k = idx % KW;
    float v;
    if (k < 128) {
        v = W_hh[n * Hh + k];
    } else {
        int j = (k - 128) >> 7, w = (k - 128) & 127;
        const float* wr = W_ih + n * 768 + 256 + 128 * j;
        float s = 0.f;
#pragma unroll 8
        for (int m = 0; m < 128; m++) s += wr[m] * d_memsm[m * Hh + w];
        v = s;
    }
    d_WcT[idx] = v;
}

__global__ void build_misc2_kernel(const float* __restrict__ W_ih,
                                   const float* __restrict__ rv0,
                                   const float* __restrict__ b_ih,
                                   const float* __restrict__ b_hh,
                                   const float* __restrict__ fc_w) {
    int gw   = (blockIdx.x * blockDim.x + threadIdx.x) >> 5;
    int lane = threadIdx.x & 31;
    if (gw < NG) {
        const float* wr = W_ih + gw * 768 + 256;
        float s = 0.f;
        for (int k = lane; k < 512; k += 32) s += rv0[k] * wr[k];
#pragma unroll
        for (int o = 16; o > 0; o >>= 1) s += __shfl_down_sync(0xffffffffu, s, o);
        if (lane == 0) {
            d_add0[gw] = s;
            d_bias[gw] = b_ih[gw] + b_hh[gw];
        }
    } else if (gw < NG + 1024) {
        int i2 = gw - NG;                         // [o][j][w]
        int o = i2 >> 9, j = (i2 >> 7) & 3, w = i2 & 127;
        float s = 0.f;
        for (int m = lane; m < 128; m += 32)
            s += d_memsm[m * Hh + w] * fc_w[o * 640 + 128 + 128 * j + m];
#pragma unroll
        for (int o2 = 16; o2 > 0; o2 >>= 1) s += __shfl_down_sync(0xffffffffu, s, o2);
        if (lane == 0) d_gv[i2] = s;
    } else if (gw < NG + 1024 + 8) {
        int i2 = (gw - NG - 1024) * 32 + lane;
        d_f0[i2] = fc_w[(i2 >> 7) * 640 + (i2 & 127)];
    }
}

__global__ void zero_state_kernel() {
    int i = blockIdx.x * blockDim.x + threadIdx.x;
    if (i < Bsz * Hh) {
        d_hA[i] = 0.f;
        d_hB[i] = 0.f;
    }
    if (i == 0) g_bar = 0u;
}

// ---------------- gx pre-pass: d_gx[t][b][n] = x[b][t] @ W_ih[:, :256]^T ----------------
__global__ void __launch_bounds__(256) gx_kernel(const float* __restrict__ x,
                                                 const float* __restrict__ W_ih) {
    extern __shared__ float sm[];
    float* As = sm;                       // [2 buf][2 grp][64][68]
    float* Bs = sm + 4 * 64 * LDCc;
    float* Cs = sm;                       // alias buf0/grp0

    const int tid  = threadIdx.x;
    const int warp = tid >> 5, lane = tid & 31;
    const int grp  = warp >> 2, wl = warp & 3;
    const int wm = (wl >> 1) * 32, wn = (wl & 1) * 32;
    const int g  = lane >> 2,  t4 = lane & 3;
    const int arow = tid >> 2, acol = (tid & 3) * 16;
    const int n0 = blockIdx.x * 64;
    const int r0 = blockIdx.y * 64;       // row in [0, 131072)

    const float* xr = x + (size_t)(r0 + arow) * DIN + acol;
    const float* wr = W_ih + (size_t)(n0 + arow) * 768 + acol;
    const uint32_t dA = (uint32_t)__cvta_generic_to_shared(As + arow * LDCc + acol);
    const uint32_t dB = (uint32_t)__cvta_generic_to_shared(Bs + arow * LDCc + acol);
    const uint32_t tileBytes = 64 * LDCc * 4;

    float acc[2][4][4];
#pragma unroll
    for (int i = 0; i < 2; i++)
#pragma unroll
        for (int j = 0; j < 4; j++)
#pragma unroll
            for (int q = 0; q < 4; q++) acc[i][j][q] = 0.f;

#pragma unroll
    for (int gg = 0; gg < 2; gg++) {
        int k0 = gg * 128;
        uint32_t da = dA + (uint32_t)gg * tileBytes;
        cp16(da,      xr + k0);      cp16(da + 16, xr + k0 + 4);
        cp16(da + 32, xr + k0 + 8);  cp16(da + 48, xr + k0 + 12);
        uint32_t db = dB + (uint32_t)gg * tileBytes;
        cp16(db,      wr + k0);      cp16(db + 16, wr + k0 + 4);
        cp16(db + 32, wr + k0 + 8);  cp16(db + 48, wr + k0 + 12);
    }
    cp_commit();

#pragma unroll
    for (int ck = 0; ck < 2; ck++) {
        int cur = ck & 1;
        if (ck == 0) {
#pragma unroll
            for (int gg = 0; gg < 2; gg++) {
                int k0 = gg * 128 + 64;
                uint32_t da = dA + (uint32_t)(2 + gg) * tileBytes;
                cp16(da,      xr + k0);      cp16(da + 16, xr + k0 + 4);
                cp16(da + 32, xr + k0 + 8);  cp16(da + 48, xr + k0 + 12);
                uint32_t db = dB + (uint32_t)(2 + gg) * tileBytes;
                cp16(db,      wr + k0);      cp16(db + 16, wr + k0 + 4);
                cp16(db + 32, wr + k0 + 8);  cp16(db + 48, wr + k0 + 12);
            }
            cp_commit();
            cp_wait1();
        } else {
            cp_wait0();
        }
        __syncthreads();
        const float* Ac = As + (cur * 2 + grp) * 64 * LDCc;
        const float* Bc = Bs + (cur * 2 + grp) * 64 * LDCc;
#pragma unroll
        for (int ks = 0; ks < 8; ks++) {
            float afr[2][4];
#pragma unroll
            for (int mi = 0; mi < 2; mi++) {
                int mr = wm + mi * 16;
                afr[mi][0] = Ac[(mr + g) * LDCc + ks * 8 + t4];
                afr[mi][1] = Ac[(mr + g + 8) * LDCc + ks * 8 + t4];
                afr[mi][2] = Ac[(mr + g) * LDCc + ks * 8 + t4 + 4];
                afr[mi][3] = Ac[(mr + g + 8) * LDCc + ks * 8 + t4 + 4];
            }
#pragma unroll
            for (int ni = 0; ni < 4; ni++) {
                int nr = wn + ni * 8;
                float bf0 = Bc[(nr + g) * LDCc + ks * 8 + t4];
                float bf1 = Bc[(nr + g) * LDCc + ks * 8 + t4 + 4];
                mma8(acc[0][ni], afr[0], bf0, bf1);
                mma8(acc[1][ni], afr[1], bf0, bf1);
            }
        }
        __syncthreads();
    }

    if (grp == 1) {
#pragma unroll
        for (int mi = 0; mi < 2; mi++)
#pragma unroll
            for (int ni = 0; ni < 4; ni++) {
                int r = wm + mi * 16 + g, cidx = wn + ni * 8 + 2 * t4;
                Cs[r * LDCc + cidx]           = acc[mi][ni][0];
                Cs[r * LDCc + cidx + 1]       = acc[mi][ni][1];
                Cs[(r + 8) * LDCc + cidx]     = acc[mi][ni][2];
                Cs[(r + 8) * LDCc + cidx + 1] = acc[mi][ni][3];
            }
    }
    __syncthreads();
    if (grp == 0) {
#pragma unroll
        for (int mi = 0; mi < 2; mi++)
#pragma unroll
            for (int ni = 0; ni < 4; ni++) {
                int r = wm + mi * 16 + g, cidx = wn + ni * 8 + 2 * t4;
                Cs[r * LDCc + cidx]           += acc[mi][ni][0];
                Cs[r * LDCc + cidx + 1]       += acc[mi][ni][1];
                Cs[(r + 8) * LDCc + cidx]     += acc[mi][ni][2];
                Cs[(r + 8) * LDCc + cidx + 1] += acc[mi][ni][3];
            }
    }
    __syncthreads();

    {
        int row = tid >> 2, col4 = (tid & 3) * 16;
        int r = r0 + row;
        int b = r >> 7, tt = r & 127;
        float* dst = d_gx + ((size_t)tt * Bsz + b) * NG + n0 + col4;
#pragma unroll
        for (int i = 0; i < 4; i++) {
            float* s = Cs + row * LDCc + col4 + 4 * i;
            ((float4*)dst)[i] = make_float4(s[0], s[1], s[2], s[3]);
        }
    }
}

// ---------------- persistent fused recurrence kernel ----------------
// Grid (8, 16), 256 threads. Block (ui, bg) owns batches {256q + bg*16 + i}
// (q<4, i<16) and gate cols {gate*128 + ui*16 + u : gate<4, u<16}.
// Per step two sub-GEMMs share one cp.async job pipeline (12 jobs):
//   jobs 0..7 : gq = hq[bg*16..+16] @ Acat^T  (16x64 C, K=512, BK=64)
//   jobs 8..11: gh = h[block rows] @ Whh^T    (64x64 C, K=128, BK=32)
// B (64x640) resident in smem for all 128 steps. c/S live in registers.
__global__ void __launch_bounds__(256) dnc_persistent() {
    extern __shared__ float sm[];
    float* A2r    = sm;                     // [3][16][68]   = 3264
    float* A1r    = sm + 3264;              // [3][64][36]   = 6912
    float* Bres   = sm + 10176;             // [64][644]     = 41216
    float* C2s    = sm + 51392;             // [4][16][68]   = 4352
    float* bias_s = sm + 55744;             // 64
    float* add0_s = sm + 55808;             // 64
    float* Cs     = A1r;                    // alias (64*68 <= 3*64*36)

    const int tid  = threadIdx.x;
    const int warp = tid >> 5, lane = tid & 31;
    const int g = lane >> 2, t4 = lane & 3;
    // gh warp roles: 2(m) x 4(n)
    const int wmh = (warp >> 2) * 32;
    const int wnh = (warp & 3) * 16;
    // gq warp roles: 4(kq) x 2(n)
    const int kq  = warp >> 1;
    const int wnq = (warp & 1) * 32;
    const int ui = blockIdx.x, bg = blockIdx.y;

    // loader mappings
    const int arow = tid >> 2, acol8 = (tid & 3) * 8;            // A1: 64x32
    const int bArow = 256 * (arow >> 4) + bg * 16 + (arow & 15); // h row for A1
    const int qrow = tid >> 4, qcol = (tid & 15) * 4;            // A2: 16x64
    const int bqoff = (bg * 16 + qrow) * 512;                    // hq row base

    if (tid < 64) {
        int ng = (tid >> 4) * 128 + ui * 16 + (tid & 15);
        bias_s[tid] = d_bias[ng];
        add0_s[tid] = d_add0[ng];
    }
    // resident B: Bres[row][k'], row -> gate (row>>4)*128 + ui*16 + (row&15)
    for (int i = tid * 4; i < 64 * KW; i += 1024) {
        int row = i / KW, col = i - row * KW;
        int n   = (row >> 4) * 128 + ui * 16 + (row & 15);
        float4 v = *(const float4*)(d_WcT + n * KW + col);
        *(float4*)(Bres + row * LDB + col) = v;
    }
    __syncthreads();

    const uint32_t a1Base = (uint32_t)__cvta_generic_to_shared(A1r + arow * LDA1 + acol8);
    const uint32_t a2Base = (uint32_t)__cvta_generic_to_shared(A2r + qrow * LDA2 + qcol);

    float c_st[4], S_st[4];
#pragma unroll
    for (int r = 0; r < 4; r++) { c_st[r] = 0.f; S_st[r] = 0.f; }

    // update-phase ownership
    const int r_up = tid >> 2, uq = tid & 3;
    const int i_up = r_up & 15;
    const int b_up = 256 * (r_up >> 4) + bg * 16 + i_up;

#pragma unroll 1
    for (int t = 0; t < Tt; t++) {
        const float* hp = (t & 1) ? d_hB : d_hA;
        float*       hw = (t & 1) ? d_hA : d_hB;

        // gx prefetch (hidden by job pipeline)
        const float* gxp = d_gx + ((size_t)t * Bsz + b_up) * NG + ui * 16 + uq * 4;
        float4 gx0 = ((const float4*)(gxp))[0];
        float4 gx1 = ((const float4*)(gxp + 128))[0];
        float4 gx2 = ((const float4*)(gxp + 256))[0];
        float4 gx3 = ((const float4*)(gxp + 384))[0];

        float accq[4][4], acch[2][2][4];
#pragma unroll
        for (int ni = 0; ni < 4; ni++)
#pragma unroll
            for (int q = 0; q < 4; q++) accq[ni][q] = 0.f;
#pragma unroll
        for (int mi = 0; mi < 2; mi++)
#pragma unroll
            for (int ni = 0; ni < 2; ni++)
#pragma unroll
                for (int q = 0; q < 4; q++) acch[mi][ni][q] = 0.f;

        auto issueJob = [&](int j) {
            if (j < 8) {   // gq A2 chunk: 16 x 64, stage j%3
                const float* src = hp + bqoff + j * 64 + qcol;
                cp16(a2Base + (uint32_t)((j % 3) * (16 * LDA2) * 4), src);
            } else {       // gh A1 chunk: 64 x 32, stage (j-8)%3
                int jj = j - 8;
                const float* src = hp + bArow * Hh + jj * 32 + acol8;
                uint32_t dst = a1Base + (uint32_t)((jj % 3) * (64 * LDA1) * 4);
                cp16(dst, src);
                cp16(dst + 16, src + 4);
            }
            cp_commit();
        };

        issueJob(0);
        issueJob(1);

#pragma unroll 1
        for (int j = 0; j < 12; j++) {
            if (j < 11) cp_wait1(); else cp_wait0();
            __syncthreads();
            if (j + 2 < 12) issueJob(j + 2);

            if (j < 8) {
                const float* Ac = A2r + (j % 3) * (16 * LDA2);
                const float* Bb = Bres + 128 + j * 64 + kq * 16;
#pragma unroll
                for (int s = 0; s < 2; s++) {
                    int ca = (kq * 2 + s) * 8 + t4;
                    float afr[4];
                    afr[0] = Ac[g * LDA2 + ca];
                    afr[1] = Ac[(g + 8) * LDA2 + ca];
                    afr[2] = Ac[g * LDA2 + ca + 4];
                    afr[3] = Ac[(g + 8) * LDA2 + ca + 4];
#pragma unroll
                    for (int ni = 0; ni < 4; ni++) {
                        const float* bp = Bb + (wnq + ni * 8 + g) * LDB + s * 8 + t4;
                        mma8(accq[ni], afr, bp[0], bp[4]);
                    }
                }
            } else {
                int jj = j - 8;
                const float* Ac = A1r + (jj % 3) * (64 * LDA1);
#pragma unroll
                for (int s = 0; s < 4; s++) {
                    int ca = s * 8 + t4;
                    float afr[2][4];
#pragma unroll
                    for (int mi = 0; mi < 2; mi++) {
                        int mr = wmh + mi * 16;
                        afr[mi][0] = Ac[(mr + g) * LDA1 + ca];
                        afr[mi][1] = Ac[(mr + g + 8) * LDA1 + ca];
                        afr[mi][2] = Ac[(mr + g) * LDA1 + ca + 4];
                        afr[mi][3] = Ac[(mr + g + 8) * LDA1 + ca + 4];
                    }
                    int kb = jj * 32 + s * 8 + t4;
#pragma unroll
                    for (int ni = 0; ni < 2; ni++) {
                        const float* bp = Bres + (wnh + ni * 8 + g) * LDB + kb;
                        mma8(acch[0][ni], afr[0], bp[0], bp[4]);
                        mma8(acch[1][ni], afr[1], bp[0], bp[4]);
                    }
                }
            }
        }
        __syncthreads();   // all compute done (A1r free -> Cs)

        // gq partials -> C2s[kq]; gh full tile -> Cs
#pragma unroll
        for (int ni = 0; ni < 4; ni++) {
            int c = wnq + ni * 8 + 2 * t4;
            float* p = C2s + kq * (16 * LDA2);
            p[g * LDA2 + c]           = accq[ni][0];
            p[g * LDA2 + c + 1]       = accq[ni][1];
            p[(g + 8) * LDA2 + c]     = accq[ni][2];
            p[(g + 8) * LDA2 + c + 1] = accq[ni][3];
        }
#pragma unroll
        for (int mi = 0; mi < 2; mi++)
#pragma unroll
            for (int ni = 0; ni < 2; ni++) {
                int r = wmh + mi * 16 + g, c = wnh + ni * 8 + 2 * t4;
                Cs[r * LDCc + c]           = acch[mi][ni][0];
                Cs[r * LDCc + c + 1]       = acch[mi][ni][1];
                Cs[(r + 8) * LDCc + c]     = acch[mi][ni][2];
                Cs[(r + 8) * LDCc + c + 1] = acch[mi][ni][3];
            }
        __syncthreads();

        // pre-reduce the 4 gq partials into C2s[0]
        {
            int id0 = tid * 4;
#pragma unroll
            for (int e = 0; e < 4; e++) {
                int id = id0 + e, rr = id >> 6, cc = id & 63;
                int o = rr * LDA2 + cc;
                C2s[o] += C2s[(16 * LDA2) + o] + C2s[2 * (16 * LDA2) + o]
                        + C2s[3 * (16 * LDA2) + o];
            }
        }
        __syncthreads();

        // fused LSTM update: thread owns (r_up, 4 u's)
        {
            const float* c2p = C2s + i_up * LDA2;
            const float* csp = Cs + r_up * LDCc;
            const float* gxa[4] = { (const float*)&gx0, (const float*)&gx1,
                                    (const float*)&gx2, (const float*)&gx3 };
            float hv[4];
#pragma unroll
            for (int e = 0; e < 4; e++) {
                int ul = uq * 4 + e;
                float ig  = csp[ul]      + c2p[ul]      + bias_s[ul]      + gxa[0][e];
                float fg  = csp[16 + ul] + c2p[16 + ul] + bias_s[16 + ul] + gxa[1][e];
                float gg2 = csp[32 + ul] + c2p[32 + ul] + bias_s[32 + ul] + gxa[2][e];
                float og  = csp[48 + ul] + c2p[48 + ul] + bias_s[48 + ul] + gxa[3][e];
                if (t == 0) {
                    ig  += add0_s[ul];      fg += add0_s[16 + ul];
                    gg2 += add0_s[32 + ul]; og += add0_s[48 + ul];
                }
                float si = 1.f / (1.f + expf(-ig));
                float sf = 1.f / (1.f + expf(-fg));
                float so = 1.f / (1.f + expf(-og));
                float c  = sf * c_st[e] + si * tanhf(gg2);
                float h  = so * tanhf(c);
                c_st[e] = c;
                S_st[e] += h;
                hv[e] = h;
            }
            float* hwp = hw + b_up * Hh + ui * 16 + uq * 4;
            *(float4*)hwp = make_float4(hv[0], hv[1], hv[2], hv[3]);
        }

        // grid barrier (monotonic counter, reset each launch)
        __threadfence();
        __syncthreads();
        if (tid == 0) {
            atomicAdd(&g_bar, 1u);
            volatile unsigned* vb = &g_bar;
            unsigned target = (unsigned)NBLK * (unsigned)(t + 1);
            while (*vb < target) { }
            __threadfence();
        }
        __syncthreads();
    }

    {
        float* Sp = d_S + b_up * Hh + ui * 16 + uq * 4;
        *(float4*)Sp = make_float4(S_st[0], S_st[1], S_st[2], S_st[3]);
    }
}

// ---------------- final output: mean over t, linear in S ----------------
__global__ void final_out_kernel(float* __restrict__ out, const float* __restrict__ fc_b) {
    int idx = blockIdx.x * blockDim.x + threadIdx.x;
    if (idx >= Bsz * 2) return;
    int b = idx >> 1, o = idx & 1;
    const float* Sb = d_S + b * Hh;
    const float* f0 = d_f0 + o * Hh;
    float s = 0.f;
#pragma unroll 8
    for (int w = 0; w < Hh; w++) s += Sb[w] * f0[w];
#pragma unroll
    for (int j = 0; j < 4; j++) {
        int bs = (4 * b + j) & (Bsz - 1);
        const float* Sp = d_S + bs * Hh;
        const float* gp = d_gv + o * 512 + j * Hh;
#pragma unroll 8
        for (int w = 0; w < Hh; w++) s += Sp[w] * gp[w];
    }
    out[idx] = s * (1.f / (float)Tt) + fc_b[o];
}

// ---------------- launch ----------------
extern "C" void kernel_launch(void* const* d_in, const int* in_sizes, int n_in,
                              void* d_out, int out_size) {
    const float* x      = (const float*)d_in[0];
    const float* memory = (const float*)d_in[1];
    const float* rv0    = (const float*)d_in[2];
    const float* W_ih   = (const float*)d_in[3];
    const float* W_hh   = (const float*)d_in[4];
    const float* b_ih   = (const float*)d_in[5];
    const float* b_hh   = (const float*)d_in[6];
    const float* fc_w   = (const float*)d_in[7];
    const float* fc_b   = (const float*)d_in[8];
    float* out = (float*)d_out;

    const int smem_pers = 55872 * 4;                 // 223,488 B
    const int smem_gx   = (8 * 64 * LDCc) * 4;       // 139,264 B
    cudaFuncSetAttribute(dnc_persistent,
                         cudaFuncAttributeMaxDynamicSharedMemorySize, smem_pers);
    cudaFuncSetAttribute(gx_kernel,
                         cudaFuncAttributeMaxDynamicSharedMemorySize, smem_gx);

    zero_state_kernel<<<(Bsz * Hh + 255) / 256, 256>>>();
    softmax_kernel<<<Hh, Hh>>>(memory);
    build_wct2_kernel<<<(NG * KW + 255) / 256, 256>>>(W_ih, W_hh);
    build_misc2_kernel<<<193, 256>>>(W_ih, rv0, b_ih, b_hh, fc_w);

    gx_kernel<<<dim3(8, (Bsz * Tt) / 64), 256, smem_gx>>>(x, W_ih);

    dnc_persistent<<<dim3(8, 16), 256, smem_pers>>>();

    final_out_kernel<<<(Bsz * 2 + 255) / 256, 256>>>(out, fc_b);
}

// round 11
// speedup vs baseline: 2.4351x; 1.0422x over previous
#include <cuda_runtime.h>
#include <cstdint>

// Problem constants
#define Bsz   1024
#define Tt    128
#define DIN   256
#define Hh    128
#define NG    512          // 4*H gates
#define KW    640          // recurrent K: h(128) + hq(512)
#define NBLK  128          // persistent grid (8 u-tiles x 16 batch-group-tiles)
#define LDA1  132          // A1 row stride (mod 32 == 4 -> conflict-free frags)
#define LDA2  516          // A2 row stride
#define LDB   644          // B row stride
#define LDCc  68           // C exchange stride

// smem layout (floats)
#define OFF_A1   0              // [64][132] = 8448   (Cs aliases: 64*68)
#define OFF_A2   8448           // [16][516] = 8256   (C2s aliases: 4*16*68)
#define OFF_B    16704          // [64][644] = 41216
#define OFF_BIAS 57920          // 64
#define OFF_ADD0 57984          // 64
#define SMEM_FLOATS 58048       // 232,192 B

// ---------------- device scratch (static, no allocations) ----------------
__device__ float d_WcT[NG * KW];        // [n][k'] folded recurrent weight (Whh | Acat)
__device__ float d_bias[NG];
__device__ float d_add0[NG];            // t==0 read-vector bias
__device__ float d_memsm[Hh * Hh];      // softmax(memory, axis=0)
__device__ float d_hA[Bsz * Hh];        // h ping-pong
__device__ float d_hB[Bsz * Hh];
__device__ float d_S[Bsz * Hh];         // sum over t of h
__device__ float d_f0[2 * Hh];
__device__ float d_gv[2 * 4 * Hh];
__device__ float d_gx[(size_t)Tt * Bsz * NG];   // precomputed x@Wx^T, [t][b][n]
__device__ unsigned g_bar;              // grid barrier counter

// ---------------- helpers ----------------
__device__ __forceinline__ void mma8(float* d, const float* a, float b0f, float b1f) {
    asm volatile(
        "mma.sync.aligned.m16n8k8.row.col.f32.tf32.tf32.f32 "
        "{%0,%1,%2,%3}, {%4,%5,%6,%7}, {%8,%9}, {%0,%1,%2,%3};\n"
        : "+f"(d[0]), "+f"(d[1]), "+f"(d[2]), "+f"(d[3])
        : "r"(__float_as_uint(a[0])), "r"(__float_as_uint(a[1])),
          "r"(__float_as_uint(a[2])), "r"(__float_as_uint(a[3])),
          "r"(__float_as_uint(b0f)), "r"(__float_as_uint(b1f)));
}

__device__ __forceinline__ void cp16(uint32_t dst, const float* src) {
    asm volatile("cp.async.cg.shared.global [%0], [%1], 16;\n" :: "r"(dst), "l"(src));
}
__device__ __forceinline__ void cp_commit() { asm volatile("cp.async.commit_group;\n" ::: "memory"); }
__device__ __forceinline__ void cp_wait0()  { asm volatile("cp.async.wait_group 0;\n" ::: "memory"); }
__device__ __forceinline__ void cp_wait1()  { asm volatile("cp.async.wait_group 1;\n" ::: "memory"); }

// ---------------- setup kernels ----------------

__global__ void softmax_kernel(const float* __restrict__ memory) {
    int w = blockIdx.x;
    int m = threadIdx.x;
    __shared__ float red[Hh];
    float v = memory[m * Hh + w];
    red[m] = v;
    __syncthreads();
    for (int s = 64; s > 0; s >>= 1) {
        if (m < s) red[m] = fmaxf(red[m], red[m + s]);
        __syncthreads();
    }
    float mx = red[0];
    __syncthreads();
    float e = expf(v - mx);
    red[m] = e;
    __syncthreads();
    for (int s = 64; s > 0; s >>= 1) {
        if (m < s) red[m] += red[m + s];
        __syncthreads();
    }
    d_memsm[m * Hh + w] = e / red[0];
}

// WcT[n][k'] : k'<128 -> W_hh[n,k'] ; else Acat[n, k'-128]
__global__ void build_wct2_kernel(const float* __restrict__ W_ih,
                                  const float* __restrict__ W_hh) {
    int idx = blockIdx.x * blockDim.x + threadIdx.x;
    if (idx >= NG * KW) return;
    int n = idx / KW, k = idx % KW;
    float v;
    if (k < 128) {
        v = W_hh[n * Hh + k];
    } else {
        int j = (k - 128) >> 7, w = (k - 128) & 127;
        const float* wr = W_ih + n * 768 + 256 + 128 * j;
        float s = 0.f;
#pragma unroll 8
        for (int m = 0; m < 128; m++) s += wr[m] * d_memsm[m * Hh + w];
        v = s;
    }
    d_WcT[idx] = v;
}

__global__ void build_misc2_kernel(const float* __restrict__ W_ih,
                                   const float* __restrict__ rv0,
                                   const float* __restrict__ b_ih,
                                   const float* __restrict__ b_hh,
                                   const float* __restrict__ fc_w) {
    int gw   = (blockIdx.x * blockDim.x + threadIdx.x) >> 5;
    int lane = threadIdx.x & 31;
    if (gw < NG) {
        const float* wr = W_ih + gw * 768 + 256;
        float s = 0.f;
        for (int k = lane; k < 512; k += 32) s += rv0[k] * wr[k];
#pragma unroll
        for (int o = 16; o > 0; o >>= 1) s += __shfl_down_sync(0xffffffffu, s, o);
        if (lane == 0) {
            d_add0[gw] = s;
            d_bias[gw] = b_ih[gw] + b_hh[gw];
        }
    } else if (gw < NG + 1024) {
        int i2 = gw - NG;                         // [o][j][w]
        int o = i2 >> 9, j = (i2 >> 7) & 3, w = i2 & 127;
        float s = 0.f;
        for (int m = lane; m < 128; m += 32)
            s += d_memsm[m * Hh + w] * fc_w[o * 640 + 128 + 128 * j + m];
#pragma unroll
        for (int o2 = 16; o2 > 0; o2 >>= 1) s += __shfl_down_sync(0xffffffffu, s, o2);
        if (lane == 0) d_gv[i2] = s;
    } else if (gw < NG + 1024 + 8) {
        int i2 = (gw - NG - 1024) * 32 + lane;
        d_f0[i2] = fc_w[(i2 >> 7) * 640 + (i2 & 127)];
    }
}

__global__ void zero_state_kernel() {
    int i = blockIdx.x * blockDim.x + threadIdx.x;
    if (i < Bsz * Hh) {
        d_hA[i] = 0.f;
        d_hB[i] = 0.f;
    }
    if (i == 0) g_bar = 0u;
}

// ---------------- gx pre-pass: d_gx[t][b][n] = x[b][t] @ W_ih[:, :256]^T ----------------
__global__ void __launch_bounds__(256) gx_kernel(const float* __restrict__ x,
                                                 const float* __restrict__ W_ih) {
    extern __shared__ float sm[];
    float* As = sm;                       // [2 buf][2 grp][64][68]
    float* Bs = sm + 4 * 64 * LDCc;
    float* Cs = sm;                       // alias buf0/grp0

    const int tid  = threadIdx.x;
    const int warp = tid >> 5, lane = tid & 31;
    const int grp  = warp >> 2, wl = warp & 3;
    const int wm = (wl >> 1) * 32, wn = (wl & 1) * 32;
    const int g  = lane >> 2,  t4 = lane & 3;
    const int arow = tid >> 2, acol = (tid & 3) * 16;
    const int n0 = blockIdx.x * 64;
    const int r0 = blockIdx.y * 64;

    const float* xr = x + (size_t)(r0 + arow) * DIN + acol;
    const float* wr = W_ih + (size_t)(n0 + arow) * 768 + acol;
    const uint32_t dA = (uint32_t)__cvta_generic_to_shared(As + arow * LDCc + acol);
    const uint32_t dB = (uint32_t)__cvta_generic_to_shared(Bs + arow * LDCc + acol);
    const uint32_t tileBytes = 64 * LDCc * 4;

    float acc[2][4][4];
#pragma unroll
    for (int i = 0; i < 2; i++)
#pragma unroll
        for (int j = 0; j < 4; j++)
#pragma unroll
            for (int q = 0; q < 4; q++) acc[i][j][q] = 0.f;

#pragma unroll
    for (int gg = 0; gg < 2; gg++) {
        int k0 = gg * 128;
        uint32_t da = dA + (uint32_t)gg * tileBytes;
        cp16(da,      xr + k0);      cp16(da + 16, xr + k0 + 4);
        cp16(da + 32, xr + k0 + 8);  cp16(da + 48, xr + k0 + 12);
        uint32_t db = dB + (uint32_t)gg * tileBytes;
        cp16(db,      wr + k0);      cp16(db + 16, wr + k0 + 4);
        cp16(db + 32, wr + k0 + 8);  cp16(db + 48, wr + k0 + 12);
    }
    cp_commit();

#pragma unroll
    for (int ck = 0; ck < 2; ck++) {
        int cur = ck & 1;
        if (ck == 0) {
#pragma unroll
            for (int gg = 0; gg < 2; gg++) {
                int k0 = gg * 128 + 64;
                uint32_t da = dA + (uint32_t)(2 + gg) * tileBytes;
                cp16(da,      xr + k0);      cp16(da + 16, xr + k0 + 4);
                cp16(da + 32, xr + k0 + 8);  cp16(da + 48, xr + k0 + 12);
                uint32_t db = dB + (uint32_t)(2 + gg) * tileBytes;
                cp16(db,      wr + k0);      cp16(db + 16, wr + k0 + 4);
                cp16(db + 32, wr + k0 + 8);  cp16(db + 48, wr + k0 + 12);
            }
            cp_commit();
            cp_wait1();
        } else {
            cp_wait0();
        }
        __syncthreads();
        const float* Ac = As + (cur * 2 + grp) * 64 * LDCc;
        const float* Bc = Bs + (cur * 2 + grp) * 64 * LDCc;
#pragma unroll
        for (int ks = 0; ks < 8; ks++) {
            float afr[2][4];
#pragma unroll
            for (int mi = 0; mi < 2; mi++) {
                int mr = wm + mi * 16;
                afr[mi][0] = Ac[(mr + g) * LDCc + ks * 8 + t4];
                afr[mi][1] = Ac[(mr + g + 8) * LDCc + ks * 8 + t4];
                afr[mi][2] = Ac[(mr + g) * LDCc + ks * 8 + t4 + 4];
                afr[mi][3] = Ac[(mr + g + 8) * LDCc + ks * 8 + t4 + 4];
            }
#pragma unroll
            for (int ni = 0; ni < 4; ni++) {
                int nr = wn + ni * 8;
                float bf0 = Bc[(nr + g) * LDCc + ks * 8 + t4];
                float bf1 = Bc[(nr + g) * LDCc + ks * 8 + t4 + 4];
                mma8(acc[0][ni], afr[0], bf0, bf1);
                mma8(acc[1][ni], afr[1], bf0, bf1);
            }
        }
        __syncthreads();
    }

    if (grp == 1) {
#pragma unroll
        for (int mi = 0; mi < 2; mi++)
#pragma unroll
            for (int ni = 0; ni < 4; ni++) {
                int r = wm + mi * 16 + g, cidx = wn + ni * 8 + 2 * t4;
                Cs[r * LDCc + cidx]           = acc[mi][ni][0];
                Cs[r * LDCc + cidx + 1]       = acc[mi][ni][1];
                Cs[(r + 8) * LDCc + cidx]     = acc[mi][ni][2];
                Cs[(r + 8) * LDCc + cidx + 1] = acc[mi][ni][3];
            }
    }
    __syncthreads();
    if (grp == 0) {
#pragma unroll
        for (int mi = 0; mi < 2; mi++)
#pragma unroll
            for (int ni = 0; ni < 4; ni++) {
                int r = wm + mi * 16 + g, cidx = wn + ni * 8 + 2 * t4;
                Cs[r * LDCc + cidx]           += acc[mi][ni][0];
                Cs[r * LDCc + cidx + 1]       += acc[mi][ni][1];
                Cs[(r + 8) * LDCc + cidx]     += acc[mi][ni][2];
                Cs[(r + 8) * LDCc + cidx + 1] += acc[mi][ni][3];
            }
    }
    __syncthreads();

    {
        int row = tid >> 2, col4 = (tid & 3) * 16;
        int r = r0 + row;
        int b = r >> 7, tt = r & 127;
        float* dst = d_gx + ((size_t)tt * Bsz + b) * NG + n0 + col4;
#pragma unroll
        for (int i = 0; i < 4; i++) {
            float* s = Cs + row * LDCc + col4 + 4 * i;
            ((float4*)dst)[i] = make_float4(s[0], s[1], s[2], s[3]);
        }
    }
}

// ---------------- persistent fused recurrence kernel ----------------
// Grid (8, 16), 256 threads. Block (ui, bg) owns batches {256q + bg*16 + i}
// (q<4, i<16) and gate cols {gate*128 + ui*16 + u}.
// Per step: ONE burst cp.async load of all A data (A1 64x128 gh rows +
// A2 16x512 hq rows), one wait, then all mma from smem:
//   gq : hq[bg*16..+16] @ Acat^T (16x64, K=512) split 4-way over K x 2 over N
//   gh : h[block rows]  @ Whh^T  (64x64, K=128) 2m x 4n warps
// B (64x640) resident in smem for all 128 steps. c/S live in registers.
__global__ void __launch_bounds__(256) dnc_persistent() {
    extern __shared__ float sm[];
    float* A1f    = sm + OFF_A1;            // [64][132]
    float* A2f    = sm + OFF_A2;            // [16][516]
    float* Bres   = sm + OFF_B;             // [64][644]
    float* bias_s = sm + OFF_BIAS;
    float* add0_s = sm + OFF_ADD0;
    float* Cs     = A1f;                    // epilogue alias (64x68)
    float* C2s    = A2f;                    // epilogue alias (4x16x68)

    const int tid  = threadIdx.x;
    const int warp = tid >> 5, lane = tid & 31;
    const int g = lane >> 2, t4 = lane & 3;
    // gh warp roles: 2(m) x 4(n)
    const int wmh = (warp >> 2) * 32;
    const int wnh = (warp & 3) * 16;
    // gq warp roles: 4(kq) x 2(n)
    const int kq  = warp >> 1;
    const int wnq = (warp & 1) * 32;
    const int ui = blockIdx.x, bg = blockIdx.y;

    // loader mappings (32 floats = 8 cp16 per thread per tile)
    const int arow = tid >> 2, acol32 = (tid & 3) * 32;          // A1: 64 rows x 128
    const int bArow = 256 * (arow >> 4) + bg * 16 + (arow & 15); // h row for A1
    const int qrow = tid >> 4, qcol32 = (tid & 15) * 32;         // A2: 16 rows x 512
    const int bqoff = (bg * 16 + qrow) * 512;                    // hq row base

    if (tid < 64) {
        int ng = (tid >> 4) * 128 + ui * 16 + (tid & 15);
        bias_s[tid] = d_bias[ng];
        add0_s[tid] = d_add0[ng];
    }
    // resident B: Bres[row][k'], row -> gate (row>>4)*128 + ui*16 + (row&15)
    for (int i = tid * 4; i < 64 * KW; i += 1024) {
        int row = i / KW, col = i - row * KW;
        int n   = (row >> 4) * 128 + ui * 16 + (row & 15);
        float4 v = *(const float4*)(d_WcT + n * KW + col);
        *(float4*)(Bres + row * LDB + col) = v;
    }
    __syncthreads();

    const uint32_t a1Base = (uint32_t)__cvta_generic_to_shared(A1f + arow * LDA1 + acol32);
    const uint32_t a2Base = (uint32_t)__cvta_generic_to_shared(A2f + qrow * LDA2 + qcol32);

    float c_st[4], S_st[4];
#pragma unroll
    for (int r = 0; r < 4; r++) { c_st[r] = 0.f; S_st[r] = 0.f; }

    // update-phase ownership
    const int r_up = tid >> 2, uq = tid & 3;
    const int i_up = r_up & 15;
    const int b_up = 256 * (r_up >> 4) + bg * 16 + i_up;

#pragma unroll 1
    for (int t = 0; t < Tt; t++) {
        const float* hp = (t & 1) ? d_hB : d_hA;
        float*       hw = (t & 1) ? d_hA : d_hB;

        // burst-load all A data for this step
        {
            const float* s1 = hp + bArow * Hh + acol32;
#pragma unroll
            for (int i = 0; i < 8; i++) cp16(a1Base + i * 16, s1 + i * 4);
            const float* s2 = hp + bqoff + qcol32;
#pragma unroll
            for (int i = 0; i < 8; i++) cp16(a2Base + i * 16, s2 + i * 4);
            cp_commit();
        }

        // gx prefetch overlaps the cp.async wait
        const float* gxp = d_gx + ((size_t)t * Bsz + b_up) * NG + ui * 16 + uq * 4;
        float4 gx0 = ((const float4*)(gxp))[0];
        float4 gx1 = ((const float4*)(gxp + 128))[0];
        float4 gx2 = ((const float4*)(gxp + 256))[0];
        float4 gx3 = ((const float4*)(gxp + 384))[0];

        float accq[4][4], acch[2][2][4];
#pragma unroll
        for (int ni = 0; ni < 4; ni++)
#pragma unroll
            for (int q = 0; q < 4; q++) accq[ni][q] = 0.f;
#pragma unroll
        for (int mi = 0; mi < 2; mi++)
#pragma unroll
            for (int ni = 0; ni < 2; ni++)
#pragma unroll
                for (int q = 0; q < 4; q++) acch[mi][ni][q] = 0.f;

        cp_wait0();
        __syncthreads();

        // ---- gq: 16x64 C, K=512, this warp does K slice [kq*16 step 64] ----
#pragma unroll
        for (int j = 0; j < 8; j++) {
#pragma unroll
            for (int s = 0; s < 2; s++) {
                int ca = j * 64 + (kq * 2 + s) * 8 + t4;
                float afr[4];
                afr[0] = A2f[g * LDA2 + ca];
                afr[1] = A2f[(g + 8) * LDA2 + ca];
                afr[2] = A2f[g * LDA2 + ca + 4];
                afr[3] = A2f[(g + 8) * LDA2 + ca + 4];
                int kb = 128 + j * 64 + kq * 16 + s * 8 + t4;
#pragma unroll
                for (int ni = 0; ni < 4; ni++) {
                    const float* bp = Bres + (wnq + ni * 8 + g) * LDB + kb;
                    mma8(accq[ni], afr, bp[0], bp[4]);
                }
            }
        }

        // ---- gh: 64x64 C, K=128 ----
#pragma unroll
        for (int s = 0; s < 16; s++) {
            int ca = s * 8 + t4;
            float afr[2][4];
#pragma unroll
            for (int mi = 0; mi < 2; mi++) {
                int mr = wmh + mi * 16;
                afr[mi][0] = A1f[(mr + g) * LDA1 + ca];
                afr[mi][1] = A1f[(mr + g + 8) * LDA1 + ca];
                afr[mi][2] = A1f[(mr + g) * LDA1 + ca + 4];
                afr[mi][3] = A1f[(mr + g + 8) * LDA1 + ca + 4];
            }
#pragma unroll
            for (int ni = 0; ni < 2; ni++) {
                const float* bp = Bres + (wnh + ni * 8 + g) * LDB + ca;
                mma8(acch[0][ni], afr[0], bp[0], bp[4]);
                mma8(acch[1][ni], afr[1], bp[0], bp[4]);
            }
        }
        __syncthreads();   // all smem A reads done -> aliases become writable

        // gq partials -> C2s[kq]; gh full tile -> Cs
#pragma unroll
        for (int ni = 0; ni < 4; ni++) {
            int c = wnq + ni * 8 + 2 * t4;
            float* p = C2s + kq * (16 * LDCc);
            p[g * LDCc + c]           = accq[ni][0];
            p[g * LDCc + c + 1]       = accq[ni][1];
            p[(g + 8) * LDCc + c]     = accq[ni][2];
            p[(g + 8) * LDCc + c + 1] = accq[ni][3];
        }
#pragma unroll
        for (int mi = 0; mi < 2; mi++)
#pragma unroll
            for (int ni = 0; ni < 2; ni++) {
                int r = wmh + mi * 16 + g, c = wnh + ni * 8 + 2 * t4;
                Cs[r * LDCc + c]           = acch[mi][ni][0];
                Cs[r * LDCc + c + 1]       = acch[mi][ni][1];
                Cs[(r + 8) * LDCc + c]     = acch[mi][ni][2];
                Cs[(r + 8) * LDCc + c + 1] = acch[mi][ni][3];
            }
        __syncthreads();

        // pre-reduce the 4 gq partials into C2s[0]
        {
            int id0 = tid * 4;
#pragma unroll
            for (int e = 0; e < 4; e++) {
                int id = id0 + e, rr = id >> 6, cc = id & 63;
                int o = rr * LDCc + cc;
                C2s[o] += C2s[(16 * LDCc) + o] + C2s[2 * (16 * LDCc) + o]
                        + C2s[3 * (16 * LDCc) + o];
            }
        }
        __syncthreads();

        // fused LSTM update: thread owns (r_up, 4 u's)
        {
            const float* c2p = C2s + i_up * LDCc;
            const float* csp = Cs + r_up * LDCc;
            const float* gxa[4] = { (const float*)&gx0, (const float*)&gx1,
                                    (const float*)&gx2, (const float*)&gx3 };
            float hv[4];
#pragma unroll
            for (int e = 0; e < 4; e++) {
                int ul = uq * 4 + e;
                float ig  = csp[ul]      + c2p[ul]      + bias_s[ul]      + gxa[0][e];
                float fg  = csp[16 + ul] + c2p[16 + ul] + bias_s[16 + ul] + gxa[1][e];
                float gg2 = csp[32 + ul] + c2p[32 + ul] + bias_s[32 + ul] + gxa[2][e];
                float og  = csp[48 + ul] + c2p[48 + ul] + bias_s[48 + ul] + gxa[3][e];
                if (t == 0) {
                    ig  += add0_s[ul];      fg += add0_s[16 + ul];
                    gg2 += add0_s[32 + ul]; og += add0_s[48 + ul];
                }
                float si = 1.f / (1.f + expf(-ig));
                float sf = 1.f / (1.f + expf(-fg));
                float so = 1.f / (1.f + expf(-og));
                float c  = sf * c_st[e] + si * tanhf(gg2);
                float h  = so * tanhf(c);
                c_st[e] = c;
                S_st[e] += h;
                hv[e] = h;
            }
            float* hwp = hw + b_up * Hh + ui * 16 + uq * 4;
            *(float4*)hwp = make_float4(hv[0], hv[1], hv[2], hv[3]);
        }

        // grid barrier (monotonic counter, reset each launch)
        __threadfence();
        __syncthreads();
        if (tid == 0) {
            atomicAdd(&g_bar, 1u);
            volatile unsigned* vb = &g_bar;
            unsigned target = (unsigned)NBLK * (unsigned)(t + 1);
            while (*vb < target) { }
            __threadfence();
        }
        __syncthreads();
    }

    {
        float* Sp = d_S + b_up * Hh + ui * 16 + uq * 4;
        *(float4*)Sp = make_float4(S_st[0], S_st[1], S_st[2], S_st[3]);
    }
}

// ---------------- final output: mean over t, linear in S ----------------
__global__ void final_out_kernel(float* __restrict__ out, const float* __restrict__ fc_b) {
    int idx = blockIdx.x * blockDim.x + threadIdx.x;
    if (idx >= Bsz * 2) return;
    int b = idx >> 1, o = idx & 1;
    const float* Sb = d_S + b * Hh;
    const float* f0 = d_f0 + o * Hh;
    float s = 0.f;
#pragma unroll 8
    for (int w = 0; w < Hh; w++) s += Sb[w] * f0[w];
#pragma unroll
    for (int j = 0; j < 4; j++) {
        int bs = (4 * b + j) & (Bsz - 1);
        const float* Sp = d_S + bs * Hh;
        const float* gp = d_gv + o * 512 + j * Hh;
#pragma unroll 8
        for (int w = 0; w < Hh; w++) s += Sp[w] * gp[w];
    }
    out[idx] = s * (1.f / (float)Tt) + fc_b[o];
}

// ---------------- launch ----------------
extern "C" void kernel_launch(void* const* d_in, const int* in_sizes, int n_in,
                              void* d_out, int out_size) {
    const float* x      = (const float*)d_in[0];
    const float* memory = (const float*)d_in[1];
    const float* rv0    = (const float*)d_in[2];
    const float* W_ih   = (const float*)d_in[3];
    const float* W_hh   = (const float*)d_in[4];
    const float* b_ih   = (const float*)d_in[5];
    const float* b_hh   = (const float*)d_in[6];
    const float* fc_w   = (const float*)d_in[7];
    const float* fc_b   = (const float*)d_in[8];
    float* out = (float*)d_out;

    const int smem_pers = SMEM_FLOATS * 4;           // 232,192 B
    const int smem_gx   = (8 * 64 * LDCc) * 4;       // 139,264 B
    cudaFuncSetAttribute(dnc_persistent,
                         cudaFuncAttributeMaxDynamicSharedMemorySize, smem_pers);
    cudaFuncSetAttribute(gx_kernel,
                         cudaFuncAttributeMaxDynamicSharedMemorySize, smem_gx);

    zero_state_kernel<<<(Bsz * Hh + 255) / 256, 256>>>();
    softmax_kernel<<<Hh, Hh>>>(memory);
    build_wct2_kernel<<<(NG * KW + 255) / 256, 256>>>(W_ih, W_hh);
    build_misc2_kernel<<<193, 256>>>(W_ih, rv0, b_ih, b_hh, fc_w);

    gx_kernel<<<dim3(8, (Bsz * Tt) / 64), 256, smem_gx>>>(x, W_ih);

    dnc_persistent<<<dim3(8, 16), 256, smem_pers>>>();

    final_out_kernel<<<(Bsz * 2 + 255) / 256, 256>>>(out, fc_b);
}

// round 12
// speedup vs baseline: 2.8646x; 1.1764x over previous
#include <cuda_runtime.h>
#include <cuda_fp16.h>
#include <cstdint>

// Problem constants
#define Bsz   1024
#define Tt    128
#define DIN   256
#define Hh    128
#define NG    512          // 4*H gates
#define KW    640          // recurrent K: h(128) + hq(512)
#define NBLK  128          // persistent grid (8 u-tiles x 16 batch-group-tiles)
#define LDCc  68           // fp32 C exchange stride
// half strides (elements)
#define LDA1H 136          // 272 B/row  -> 68 words  == 4 mod 32 (conflict-free)
#define LDA2H 552          // 1104 B/row -> 276 words == 20 mod 32 (conflict-free)
#define LDBH  648          // 1296 B/row -> 324 words == 4 mod 32 (conflict-free)

// smem layout (bytes)
#define OFF_A1   0              // A1h [64][136] halves = 17408 B (alias Cs 64x68 f32)
#define OFF_A2   17408          // A2h [16][552] halves = 17664 B (alias C2s 4x16x68 f32)
#define OFF_B    35072          // Bh  [64][648] halves = 82944 B
#define OFF_BIAS 118016         // 64 f32
#define OFF_ADD0 118272         // 64 f32
#define SMEM_BYTES 118528

// ---------------- device scratch (static, no allocations) ----------------
__device__ __half d_WcTh[NG * KW];      // [n][k'] folded recurrent weight (half)
__device__ float  d_bias[NG];
__device__ float  d_add0[NG];           // t==0 read-vector bias
__device__ float  d_memsm[Hh * Hh];     // softmax(memory, axis=0)
__device__ __half d_hA[Bsz * Hh];       // h ping-pong (half)
__device__ __half d_hB[Bsz * Hh];
__device__ float  d_S[Bsz * Hh];        // sum over t of h (fp32)
__device__ float  d_f0[2 * Hh];
__device__ float  d_gv[2 * 4 * Hh];
__device__ float  d_gx[(size_t)Tt * Bsz * NG];   // precomputed x@Wx^T, [t][b][n]
__device__ unsigned g_bar;              // grid barrier counter

// ---------------- helpers ----------------
__device__ __forceinline__ void mma8(float* d, const float* a, float b0f, float b1f) {
    asm volatile(
        "mma.sync.aligned.m16n8k8.row.col.f32.tf32.tf32.f32 "
        "{%0,%1,%2,%3}, {%4,%5,%6,%7}, {%8,%9}, {%0,%1,%2,%3};\n"
        : "+f"(d[0]), "+f"(d[1]), "+f"(d[2]), "+f"(d[3])
        : "r"(__float_as_uint(a[0])), "r"(__float_as_uint(a[1])),
          "r"(__float_as_uint(a[2])), "r"(__float_as_uint(a[3])),
          "r"(__float_as_uint(b0f)), "r"(__float_as_uint(b1f)));
}

__device__ __forceinline__ void mma16(float* d, const unsigned* a, unsigned b0, unsigned b1) {
    asm volatile(
        "mma.sync.aligned.m16n8k16.row.col.f32.f16.f16.f32 "
        "{%0,%1,%2,%3}, {%4,%5,%6,%7}, {%8,%9}, {%0,%1,%2,%3};\n"
        : "+f"(d[0]), "+f"(d[1]), "+f"(d[2]), "+f"(d[3])
        : "r"(a[0]), "r"(a[1]), "r"(a[2]), "r"(a[3]), "r"(b0), "r"(b1));
}

__device__ __forceinline__ void cp16(uint32_t dst, const void* src) {
    asm volatile("cp.async.cg.shared.global [%0], [%1], 16;\n" :: "r"(dst), "l"(src));
}
__device__ __forceinline__ void cp_commit() { asm volatile("cp.async.commit_group;\n" ::: "memory"); }
__device__ __forceinline__ void cp_wait0()  { asm volatile("cp.async.wait_group 0;\n" ::: "memory"); }
__device__ __forceinline__ void cp_wait1()  { asm volatile("cp.async.wait_group 1;\n" ::: "memory"); }

// ---------------- setup kernels ----------------

__global__ void softmax_kernel(const float* __restrict__ memory) {
    int w = blockIdx.x;
    int m = threadIdx.x;
    __shared__ float red[Hh];
    float v = memory[m * Hh + w];
    red[m] = v;
    __syncthreads();
    for (int s = 64; s > 0; s >>= 1) {
        if (m < s) red[m] = fmaxf(red[m], red[m + s]);
        __syncthreads();
    }
    float mx = red[0];
    __syncthreads();
    float e = expf(v - mx);
    red[m] = e;
    __syncthreads();
    for (int s = 64; s > 0; s >>= 1) {
        if (m < s) red[m] += red[m + s];
        __syncthreads();
    }
    d_memsm[m * Hh + w] = e / red[0];
}

// WcTh[n][k'] : k'<128 -> W_hh[n,k'] ; else Acat[n, k'-128]
__global__ void build_wct2_kernel(const float* __restrict__ W_ih,
                                  const float* __restrict__ W_hh) {
    int idx = blockIdx.x * blockDim.x + threadIdx.x;
    if (idx >= NG * KW) return;
    int n = idx / KW, k = idx % KW;
    float v;
    if (k < 128) {
        v = W_hh[n * Hh + k];
    } else {
        int j = (k - 128) >> 7, w = (k - 128) & 127;
        const float* wr = W_ih + n * 768 + 256 + 128 * j;
        float s = 0.f;
#pragma unroll 8
        for (int m = 0; m < 128; m++) s += wr[m] * d_memsm[m * Hh + w];
        v = s;
    }
    d_WcTh[idx] = __float2half_rn(v);
}

__global__ void build_misc2_kernel(const float* __restrict__ W_ih,
                                   const float* __restrict__ rv0,
                                   const float* __restrict__ b_ih,
                                   const float* __restrict__ b_hh,
                                   const float* __restrict__ fc_w) {
    int gw   = (blockIdx.x * blockDim.x + threadIdx.x) >> 5;
    int lane = threadIdx.x & 31;
    if (gw < NG) {
        const float* wr = W_ih + gw * 768 + 256;
        float s = 0.f;
        for (int k = lane; k < 512; k += 32) s += rv0[k] * wr[k];
#pragma unroll
        for (int o = 16; o > 0; o >>= 1) s += __shfl_down_sync(0xffffffffu, s, o);
        if (lane == 0) {
            d_add0[gw] = s;
            d_bias[gw] = b_ih[gw] + b_hh[gw];
        }
    } else if (gw < NG + 1024) {
        int i2 = gw - NG;                         // [o][j][w]
        int o = i2 >> 9, j = (i2 >> 7) & 3, w = i2 & 127;
        float s = 0.f;
        for (int m = lane; m < 128; m += 32)
            s += d_memsm[m * Hh + w] * fc_w[o * 640 + 128 + 128 * j + m];
#pragma unroll
        for (int o2 = 16; o2 > 0; o2 >>= 1) s += __shfl_down_sync(0xffffffffu, s, o2);
        if (lane == 0) d_gv[i2] = s;
    } else if (gw < NG + 1024 + 8) {
        int i2 = (gw - NG - 1024) * 32 + lane;
        d_f0[i2] = fc_w[(i2 >> 7) * 640 + (i2 & 127)];
    }
}

__global__ void zero_state_kernel() {
    int i = blockIdx.x * blockDim.x + threadIdx.x;
    if (i < Bsz * Hh) {
        d_hA[i] = __float2half(0.f);
        d_hB[i] = __float2half(0.f);
    }
    if (i == 0) g_bar = 0u;
}

// ---------------- gx pre-pass: d_gx[t][b][n] = x[b][t] @ W_ih[:, :256]^T ----------------
__global__ void __launch_bounds__(256) gx_kernel(const float* __restrict__ x,
                                                 const float* __restrict__ W_ih) {
    extern __shared__ float sm[];
    float* As = sm;                       // [2 buf][2 grp][64][68]
    float* Bs = sm + 4 * 64 * LDCc;
    float* Cs = sm;                       // alias buf0/grp0

    const int tid  = threadIdx.x;
    const int warp = tid >> 5, lane = tid & 31;
    const int grp  = warp >> 2, wl = warp & 3;
    const int wm = (wl >> 1) * 32, wn = (wl & 1) * 32;
    const int g  = lane >> 2,  t4 = lane & 3;
    const int arow = tid >> 2, acol = (tid & 3) * 16;
    const int n0 = blockIdx.x * 64;
    const int r0 = blockIdx.y * 64;

    const float* xr = x + (size_t)(r0 + arow) * DIN + acol;
    const float* wr = W_ih + (size_t)(n0 + arow) * 768 + acol;
    const uint32_t dA = (uint32_t)__cvta_generic_to_shared(As + arow * LDCc + acol);
    const uint32_t dB = (uint32_t)__cvta_generic_to_shared(Bs + arow * LDCc + acol);
    const uint32_t tileBytes = 64 * LDCc * 4;

    float acc[2][4][4];
#pragma unroll
    for (int i = 0; i < 2; i++)
#pragma unroll
        for (int j = 0; j < 4; j++)
#pragma unroll
            for (int q = 0; q < 4; q++) acc[i][j][q] = 0.f;

#pragma unroll
    for (int gg = 0; gg < 2; gg++) {
        int k0 = gg * 128;
        uint32_t da = dA + (uint32_t)gg * tileBytes;
        cp16(da,      xr + k0);      cp16(da + 16, xr + k0 + 4);
        cp16(da + 32, xr + k0 + 8);  cp16(da + 48, xr + k0 + 12);
        uint32_t db = dB + (uint32_t)gg * tileBytes;
        cp16(db,      wr + k0);      cp16(db + 16, wr + k0 + 4);
        cp16(db + 32, wr + k0 + 8);  cp16(db + 48, wr + k0 + 12);
    }
    cp_commit();

#pragma unroll
    for (int ck = 0; ck < 2; ck++) {
        int cur = ck & 1;
        if (ck == 0) {
#pragma unroll
            for (int gg = 0; gg < 2; gg++) {
                int k0 = gg * 128 + 64;
                uint32_t da = dA + (uint32_t)(2 + gg) * tileBytes;
                cp16(da,      xr + k0);      cp16(da + 16, xr + k0 + 4);
                cp16(da + 32, xr + k0 + 8);  cp16(da + 48, xr + k0 + 12);
                uint32_t db = dB + (uint32_t)(2 + gg) * tileBytes;
                cp16(db,      wr + k0);      cp16(db + 16, wr + k0 + 4);
                cp16(db + 32, wr + k0 + 8);  cp16(db + 48, wr + k0 + 12);
            }
            cp_commit();
            cp_wait1();
        } else {
            cp_wait0();
        }
        __syncthreads();
        const float* Ac = As + (cur * 2 + grp) * 64 * LDCc;
        const float* Bc = Bs + (cur * 2 + grp) * 64 * LDCc;
#pragma unroll
        for (int ks = 0; ks < 8; ks++) {
            float afr[2][4];
#pragma unroll
            for (int mi = 0; mi < 2; mi++) {
                int mr = wm + mi * 16;
                afr[mi][0] = Ac[(mr + g) * LDCc + ks * 8 + t4];
                afr[mi][1] = Ac[(mr + g + 8) * LDCc + ks * 8 + t4];
                afr[mi][2] = Ac[(mr + g) * LDCc + ks * 8 + t4 + 4];
                afr[mi][3] = Ac[(mr + g + 8) * LDCc + ks * 8 + t4 + 4];
            }
#pragma unroll
            for (int ni = 0; ni < 4; ni++) {
                int nr = wn + ni * 8;
                float bf0 = Bc[(nr + g) * LDCc + ks * 8 + t4];
                float bf1 = Bc[(nr + g) * LDCc + ks * 8 + t4 + 4];
                mma8(acc[0][ni], afr[0], bf0, bf1);
                mma8(acc[1][ni], afr[1], bf0, bf1);
            }
        }
        __syncthreads();
    }

    if (grp == 1) {
#pragma unroll
        for (int mi = 0; mi < 2; mi++)
#pragma unroll
            for (int ni = 0; ni < 4; ni++) {
                int r = wm + mi * 16 + g, cidx = wn + ni * 8 + 2 * t4;
                Cs[r * LDCc + cidx]           = acc[mi][ni][0];
                Cs[r * LDCc + cidx + 1]       = acc[mi][ni][1];
                Cs[(r + 8) * LDCc + cidx]     = acc[mi][ni][2];
                Cs[(r + 8) * LDCc + cidx + 1] = acc[mi][ni][3];
            }
    }
    __syncthreads();
    if (grp == 0) {
#pragma unroll
        for (int mi = 0; mi < 2; mi++)
#pragma unroll
            for (int ni = 0; ni < 4; ni++) {
                int r = wm + mi * 16 + g, cidx = wn + ni * 8 + 2 * t4;
                Cs[r * LDCc + cidx]           += acc[mi][ni][0];
                Cs[r * LDCc + cidx + 1]       += acc[mi][ni][1];
                Cs[(r + 8) * LDCc + cidx]     += acc[mi][ni][2];
                Cs[(r + 8) * LDCc + cidx + 1] += acc[mi][ni][3];
            }
    }
    __syncthreads();

    {
        int row = tid >> 2, col4 = (tid & 3) * 16;
        int r = r0 + row;
        int b = r >> 7, tt = r & 127;
        float* dst = d_gx + ((size_t)tt * Bsz + b) * NG + n0 + col4;
#pragma unroll
        for (int i = 0; i < 4; i++) {
            float* s = Cs + row * LDCc + col4 + 4 * i;
            ((float4*)dst)[i] = make_float4(s[0], s[1], s[2], s[3]);
        }
    }
}

// ---------------- persistent fused recurrence kernel (fp16 MMA) ----------------
// Grid (8, 16), 256 threads. Block (ui, bg) owns batches {256q + bg*16 + i}
// and gate cols {gate*128 + ui*16 + u}. Per step: one burst cp.async load of
// A1 (64x128 h halves) + A2 (16x512 hq halves), one wait, then:
//   gq : hq @ Acat^T (16x64, K=512) split 4-way over K x 2 over N  (m16n8k16)
//   gh : h  @ Whh^T  (64x64, K=128) 2m x 4n warps                  (m16n8k16)
// B (64x640 half) resident in smem. c/S fp32 in registers. h stored fp16.
__global__ void __launch_bounds__(256) dnc_persistent() {
    extern __shared__ unsigned char smc[];
    __half* A1h   = (__half*)(smc + OFF_A1);    // [64][136]
    __half* A2h   = (__half*)(smc + OFF_A2);    // [16][552]
    __half* Bh    = (__half*)(smc + OFF_B);     // [64][648]
    float*  Cs    = (float*)(smc + OFF_A1);     // epilogue alias [64][68]
    float*  C2s   = (float*)(smc + OFF_A2);     // epilogue alias [4][16][68]
    float*  bias_s = (float*)(smc + OFF_BIAS);
    float*  add0_s = (float*)(smc + OFF_ADD0);

    const int tid  = threadIdx.x;
    const int warp = tid >> 5, lane = tid & 31;
    const int g = lane >> 2, t4 = lane & 3;
    // gh warp roles: 2(m) x 4(n)
    const int wmh = (warp >> 2) * 32;
    const int wnh = (warp & 3) * 16;
    // gq warp roles: 4(kq contiguous 128-K slices) x 2(n)
    const int kq  = warp >> 1;
    const int wnq = (warp & 1) * 32;
    const int ui = blockIdx.x, bg = blockIdx.y;

    // loader mappings (32 halves = 4 cp16 per thread per tile)
    const int arow = tid >> 2, acol32 = (tid & 3) * 32;          // A1: 64 rows x 128
    const int bArow = 256 * (arow >> 4) + bg * 16 + (arow & 15); // h row for A1
    const int qrow = tid >> 4, qcol32 = (tid & 15) * 32;         // A2: 16 rows x 512
    const int bqoff = (bg * 16 + qrow) * 512;                    // hq row base (halves)

    if (tid < 64) {
        int ng = (tid >> 4) * 128 + ui * 16 + (tid & 15);
        bias_s[tid] = d_bias[ng];
        add0_s[tid] = d_add0[ng];
    }
    // resident B (half): Bh[row][k'], row -> gate (row>>4)*128 + ui*16 + (row&15)
    for (int i = tid * 8; i < 64 * KW; i += 2048) {
        int row = i / KW, col = i - row * KW;
        int n   = (row >> 4) * 128 + ui * 16 + (row & 15);
        uint4 v = *(const uint4*)(d_WcTh + n * KW + col);
        *(uint4*)(Bh + row * LDBH + col) = v;
    }
    __syncthreads();

    const uint32_t a1Base = (uint32_t)__cvta_generic_to_shared(A1h + arow * LDA1H + acol32);
    const uint32_t a2Base = (uint32_t)__cvta_generic_to_shared(A2h + qrow * LDA2H + qcol32);

    float c_st[4], S_st[4];
#pragma unroll
    for (int r = 0; r < 4; r++) { c_st[r] = 0.f; S_st[r] = 0.f; }

    // update-phase ownership
    const int r_up = tid >> 2, uq = tid & 3;
    const int i_up = r_up & 15;
    const int b_up = 256 * (r_up >> 4) + bg * 16 + i_up;

#pragma unroll 1
    for (int t = 0; t < Tt; t++) {
        const __half* hp = (t & 1) ? d_hB : d_hA;
        __half*       hw = (t & 1) ? d_hA : d_hB;

        // burst-load all A data for this step (32 KB/block)
        {
            const __half* s1 = hp + bArow * Hh + acol32;
#pragma unroll
            for (int i = 0; i < 4; i++) cp16(a1Base + i * 16, s1 + i * 8);
            const __half* s2 = hp + bqoff + qcol32;
#pragma unroll
            for (int i = 0; i < 4; i++) cp16(a2Base + i * 16, s2 + i * 8);
            cp_commit();
        }

        // gx prefetch overlaps the cp.async wait
        const float* gxp = d_gx + ((size_t)t * Bsz + b_up) * NG + ui * 16 + uq * 4;
        float4 gx0 = ((const float4*)(gxp))[0];
        float4 gx1 = ((const float4*)(gxp + 128))[0];
        float4 gx2 = ((const float4*)(gxp + 256))[0];
        float4 gx3 = ((const float4*)(gxp + 384))[0];

        float accq[4][4], acch[2][2][4];
#pragma unroll
        for (int ni = 0; ni < 4; ni++)
#pragma unroll
            for (int q = 0; q < 4; q++) accq[ni][q] = 0.f;
#pragma unroll
        for (int mi = 0; mi < 2; mi++)
#pragma unroll
            for (int ni = 0; ni < 2; ni++)
#pragma unroll
                for (int q = 0; q < 4; q++) acch[mi][ni][q] = 0.f;

        cp_wait0();
        __syncthreads();

        // ---- gq: 16x64 C, K slice [kq*128, +128), warp covers n [wnq, +32) ----
#pragma unroll
        for (int j = 0; j < 8; j++) {
            int ka = kq * 128 + j * 16 + 2 * t4;
            unsigned afr[4];
            afr[0] = *(const unsigned*)(A2h + g * LDA2H + ka);
            afr[1] = *(const unsigned*)(A2h + (g + 8) * LDA2H + ka);
            afr[2] = *(const unsigned*)(A2h + g * LDA2H + ka + 8);
            afr[3] = *(const unsigned*)(A2h + (g + 8) * LDA2H + ka + 8);
            int kb = 128 + kq * 128 + j * 16 + 2 * t4;
#pragma unroll
            for (int ni = 0; ni < 4; ni++) {
                const __half* bp = Bh + (wnq + ni * 8 + g) * LDBH + kb;
                unsigned b0 = *(const unsigned*)(bp);
                unsigned b1 = *(const unsigned*)(bp + 8);
                mma16(accq[ni], afr, b0, b1);
            }
        }

        // ---- gh: 64x64 C, K=128, warp tile 32m x 16n ----
#pragma unroll
        for (int j = 0; j < 8; j++) {
            int ka = j * 16 + 2 * t4;
            unsigned afr[2][4];
#pragma unroll
            for (int mi = 0; mi < 2; mi++) {
                int mr = wmh + mi * 16;
                afr[mi][0] = *(const unsigned*)(A1h + (mr + g) * LDA1H + ka);
                afr[mi][1] = *(const unsigned*)(A1h + (mr + g + 8) * LDA1H + ka);
                afr[mi][2] = *(const unsigned*)(A1h + (mr + g) * LDA1H + ka + 8);
                afr[mi][3] = *(const unsigned*)(A1h + (mr + g + 8) * LDA1H + ka + 8);
            }
#pragma unroll
            for (int ni = 0; ni < 2; ni++) {
                const __half* bp = Bh + (wnh + ni * 8 + g) * LDBH + ka;
                unsigned b0 = *(const unsigned*)(bp);
                unsigned b1 = *(const unsigned*)(bp + 8);
                mma16(acch[0][ni], afr[0], b0, b1);
                mma16(acch[1][ni], afr[1], b0, b1);
            }
        }
        __syncthreads();   // all smem A reads done -> aliases become writable

        // gq partials -> C2s[kq]; gh full tile -> Cs
#pragma unroll
        for (int ni = 0; ni < 4; ni++) {
            int c = wnq + ni * 8 + 2 * t4;
            float* p = C2s + kq * (16 * LDCc);
            p[g * LDCc + c]           = accq[ni][0];
            p[g * LDCc + c + 1]       = accq[ni][1];
            p[(g + 8) * LDCc + c]     = accq[ni][2];
            p[(g + 8) * LDCc + c + 1] = accq[ni][3];
        }
#pragma unroll
        for (int mi = 0; mi < 2; mi++)
#pragma unroll
            for (int ni = 0; ni < 2; ni++) {
                int r = wmh + mi * 16 + g, c = wnh + ni * 8 + 2 * t4;
                Cs[r * LDCc + c]           = acch[mi][ni][0];
                Cs[r * LDCc + c + 1]       = acch[mi][ni][1];
                Cs[(r + 8) * LDCc + c]     = acch[mi][ni][2];
                Cs[(r + 8) * LDCc + c + 1] = acch[mi][ni][3];
            }
        __syncthreads();

        // pre-reduce the 4 gq partials into C2s[0]
        {
            int id0 = tid * 4;
#pragma unroll
            for (int e = 0; e < 4; e++) {
                int id = id0 + e, rr = id >> 6, cc = id & 63;
                int o = rr * LDCc + cc;
                C2s[o] += C2s[(16 * LDCc) + o] + C2s[2 * (16 * LDCc) + o]
                        + C2s[3 * (16 * LDCc) + o];
            }
        }
        __syncthreads();

        // fused LSTM update: thread owns (r_up, 4 u's)
        {
            const float* c2p = C2s + i_up * LDCc;
            const float* csp = Cs + r_up * LDCc;
            const float* gxa[4] = { (const float*)&gx0, (const float*)&gx1,
                                    (const float*)&gx2, (const float*)&gx3 };
            float hv[4];
#pragma unroll
            for (int e = 0; e < 4; e++) {
                int ul = uq * 4 + e;
                float ig  = csp[ul]      + c2p[ul]      + bias_s[ul]      + gxa[0][e];
                float fg  = csp[16 + ul] + c2p[16 + ul] + bias_s[16 + ul] + gxa[1][e];
                float gg2 = csp[32 + ul] + c2p[32 + ul] + bias_s[32 + ul] + gxa[2][e];
                float og  = csp[48 + ul] + c2p[48 + ul] + bias_s[48 + ul] + gxa[3][e];
                if (t == 0) {
                    ig  += add0_s[ul];      fg += add0_s[16 + ul];
                    gg2 += add0_s[32 + ul]; og += add0_s[48 + ul];
                }
                float si = 1.f / (1.f + expf(-ig));
                float sf = 1.f / (1.f + expf(-fg));
                float so = 1.f / (1.f + expf(-og));
                float c  = sf * c_st[e] + si * tanhf(gg2);
                float h  = so * tanhf(c);
                c_st[e] = c;
                S_st[e] += h;
                hv[e] = h;
            }
            __half2 p0 = __floats2half2_rn(hv[0], hv[1]);
            __half2 p1 = __floats2half2_rn(hv[2], hv[3]);
            __half* hwp = hw + b_up * Hh + ui * 16 + uq * 4;
            *(uint2*)hwp = make_uint2(*(unsigned*)&p0, *(unsigned*)&p1);
        }

        // grid barrier (monotonic counter, reset each launch)
        __threadfence();
        __syncthreads();
        if (tid == 0) {
            atomicAdd(&g_bar, 1u);
            volatile unsigned* vb = &g_bar;
            unsigned target = (unsigned)NBLK * (unsigned)(t + 1);
            while (*vb < target) { }
            __threadfence();
        }
        __syncthreads();
    }

    {
        float* Sp = d_S + b_up * Hh + ui * 16 + uq * 4;
        *(float4*)Sp = make_float4(S_st[0], S_st[1], S_st[2], S_st[3]);
    }
}

// ---------------- final output: mean over t, linear in S ----------------
__global__ void final_out_kernel(float* __restrict__ out, const float* __restrict__ fc_b) {
    int idx = blockIdx.x * blockDim.x + threadIdx.x;
    if (idx >= Bsz * 2) return;
    int b = idx >> 1, o = idx & 1;
    const float* Sb = d_S + b * Hh;
    const float* f0 = d_f0 + o * Hh;
    float s = 0.f;
#pragma unroll 8
    for (int w = 0; w < Hh; w++) s += Sb[w] * f0[w];
#pragma unroll
    for (int j = 0; j < 4; j++) {
        int bs = (4 * b + j) & (Bsz - 1);
        const float* Sp = d_S + bs * Hh;
        const float* gp = d_gv + o * 512 + j * Hh;
#pragma unroll 8
        for (int w = 0; w < Hh; w++) s += Sp[w] * gp[w];
    }
    out[idx] = s * (1.f / (float)Tt) + fc_b[o];
}

// ---------------- launch ----------------
extern "C" void kernel_launch(void* const* d_in, const int* in_sizes, int n_in,
                              void* d_out, int out_size) {
    const float* x      = (const float*)d_in[0];
    const float* memory = (const float*)d_in[1];
    const float* rv0    = (const float*)d_in[2];
    const float* W_ih   = (const float*)d_in[3];
    const float* W_hh   = (const float*)d_in[4];
    const float* b_ih   = (const float*)d_in[5];
    const float* b_hh   = (const float*)d_in[6];
    const float* fc_w   = (const float*)d_in[7];
    const float* fc_b   = (const float*)d_in[8];
    float* out = (float*)d_out;

    const int smem_pers = SMEM_BYTES;                // 118,528 B
    const int smem_gx   = (8 * 64 * LDCc) * 4;       // 139,264 B
    cudaFuncSetAttribute(dnc_persistent,
                         cudaFuncAttributeMaxDynamicSharedMemorySize, smem_pers);
    cudaFuncSetAttribute(gx_kernel,
                         cudaFuncAttributeMaxDynamicSharedMemorySize, smem_gx);

    zero_state_kernel<<<(Bsz * Hh + 255) / 256, 256>>>();
    softmax_kernel<<<Hh, Hh>>>(memory);
    build_wct2_kernel<<<(NG * KW + 255) / 256, 256>>>(W_ih, W_hh);
    build_misc2_kernel<<<193, 256>>>(W_ih, rv0, b_ih, b_hh, fc_w);

    gx_kernel<<<dim3(8, (Bsz * Tt) / 64), 256, smem_gx>>>(x, W_ih);

    dnc_persistent<<<dim3(8, 16), 256, smem_pers>>>();

    final_out_kernel<<<(Bsz * 2 + 255) / 256, 256>>>(out, fc_b);
}

// round 16
// speedup vs baseline: 4.0094x; 1.3997x over previous
#include <cuda_runtime.h>
#include <cuda_fp16.h>
#include <cstdint>

// Problem constants
#define Bsz   1024
#define Tt    128
#define DIN   256
#define Hh    128
#define NG    512          // 4*H gates
#define KW    640          // recurrent K: h(128) + hq(512)
#define NBLK  128          // persistent grid (8 u-tiles x 16 batch-group-tiles)
#define LDCc  68           // fp32 C exchange stride
// half strides (elements)
#define LDA1H 136          // 272 B/row
#define LDA2H 552          // 1104 B/row
#define LDBH  648          // 1296 B/row
#define LDXH  264          // gx tiles: 528 B/row

// persistent smem layout (bytes)
#define OFF_A1   0              // A1h [64][136] halves = 17408 B (alias Cs 64x68 f32)
#define OFF_A2   17408          // A2h [16][552] halves = 17664 B (alias C2s 4x16x68 f32)
#define OFF_B    35072          // Bh  [64][648] halves = 82944 B
#define OFF_BIAS 118016         // 64 f32
#define OFF_ADD0 118272         // 64 f32
#define SMEM_BYTES 118528

// ---------------- device scratch (static, no allocations) ----------------
__device__ __half d_WcTh[NG * KW];      // [n][k'] folded recurrent weight (half)
__device__ float  d_bias[NG];
__device__ float  d_add0[NG];           // t==0 read-vector bias
__device__ float  d_memsm[Hh * Hh];     // softmax(memory, axis=0)
__device__ __half d_hA[Bsz * Hh];       // h ping-pong (half)
__device__ __half d_hB[Bsz * Hh];
__device__ float  d_S[Bsz * Hh];        // sum over t of h (fp32)
__device__ float  d_f0[2 * Hh];
__device__ float  d_gv[2 * 4 * Hh];
__device__ __half d_xh[(size_t)Bsz * Tt * DIN];  // x in fp16
__device__ __half d_wxh[NG * DIN];               // W_ih[:, :256] in fp16
__device__ float  d_gx[(size_t)Tt * Bsz * NG];   // precomputed x@Wx^T, [t][b][n]
__device__ unsigned g_bar;              // grid barrier counter

// ---------------- helpers ----------------
__device__ __forceinline__ void mma16(float* d, const unsigned* a, unsigned b0, unsigned b1) {
    asm volatile(
        "mma.sync.aligned.m16n8k16.row.col.f32.f16.f16.f32 "
        "{%0,%1,%2,%3}, {%4,%5,%6,%7}, {%8,%9}, {%0,%1,%2,%3};\n"
        : "+f"(d[0]), "+f"(d[1]), "+f"(d[2]), "+f"(d[3])
        : "r"(a[0]), "r"(a[1]), "r"(a[2]), "r"(a[3]), "r"(b0), "r"(b1));
}

__device__ __forceinline__ void cp16(uint32_t dst, const void* src) {
    asm volatile("cp.async.cg.shared.global [%0], [%1], 16;\n" :: "r"(dst), "l"(src));
}
__device__ __forceinline__ void cp_commit() { asm volatile("cp.async.commit_group;\n" ::: "memory"); }
__device__ __forceinline__ void cp_wait0()  { asm volatile("cp.async.wait_group 0;\n" ::: "memory"); }

__device__ __forceinline__ float tanh_f(float x) {
    float y;
    asm("tanh.approx.f32 %0, %1;" : "=f"(y) : "f"(x));
    return y;
}
__device__ __forceinline__ float sigm_f(float x) {
    return __fdividef(1.f, 1.f + __expf(-x));
}

__device__ __forceinline__ void red_release_add(unsigned* p, unsigned v) {
    asm volatile("red.release.gpu.add.u32 [%0], %1;" :: "l"(p), "r"(v) : "memory");
}
__device__ __forceinline__ unsigned ld_acquire(unsigned* p) {
    unsigned v;
    asm volatile("ld.acquire.gpu.u32 %0, [%1];" : "=r"(v) : "l"(p) : "memory");
    return v;
}

// ---------------- setup kernels ----------------

__global__ void softmax_kernel(const float* __restrict__ memory) {
    int w = blockIdx.x;
    int m = threadIdx.x;
    __shared__ float red[Hh];
    float v = memory[m * Hh + w];
    red[m] = v;
    __syncthreads();
    for (int s = 64; s > 0; s >>= 1) {
        if (m < s) red[m] = fmaxf(red[m], red[m + s]);
        __syncthreads();
    }
    float mx = red[0];
    __syncthreads();
    float e = expf(v - mx);
    red[m] = e;
    __syncthreads();
    for (int s = 64; s > 0; s >>= 1) {
        if (m < s) red[m] += red[m + s];
        __syncthreads();
    }
    d_memsm[m * Hh + w] = e / red[0];
}

// WcTh[n][k'] : k'<128 -> W_hh[n,k'] ; else Acat[n, k'-128]
__global__ void build_wct2_kernel(const float* __restrict__ W_ih,
                                  const float* __restrict__ W_hh) {
    int idx = blockIdx.x * blockDim.x + threadIdx.x;
    if (idx >= NG * KW) return;
    int n = idx / KW, k = idx % KW;
    float v;
    if (k < 128) {
        v = W_hh[n * Hh + k];
    } else {
        int j = (k - 128) >> 7, w = (k - 128) & 127;
        const float* wr = W_ih + n * 768 + 256 + 128 * j;
        float s = 0.f;
#pragma unroll 8
        for (int m = 0; m < 128; m++) s += wr[m] * d_memsm[m * Hh + w];
        v = s;
    }
    d_WcTh[idx] = __float2half_rn(v);
}

__global__ void build_misc2_kernel(const float* __restrict__ W_ih,
                                   const float* __restrict__ rv0,
                                   const float* __restrict__ b_ih,
                                   const float* __restrict__ b_hh,
                                   const float* __restrict__ fc_w) {
    int gw   = (blockIdx.x * blockDim.x + threadIdx.x) >> 5;
    int lane = threadIdx.x & 31;
    if (gw < NG) {
        const float* wr = W_ih + gw * 768 + 256;
        float s = 0.f;
        for (int k = lane; k < 512; k += 32) s += rv0[k] * wr[k];
#pragma unroll
        for (int o = 16; o > 0; o >>= 1) s += __shfl_down_sync(0xffffffffu, s, o);
        if (lane == 0) {
            d_add0[gw] = s;
            d_bias[gw] = b_ih[gw] + b_hh[gw];
        }
    } else if (gw < NG + 1024) {
        int i2 = gw - NG;                         // [o][j][w]
        int o = i2 >> 9, j = (i2 >> 7) & 3, w = i2 & 127;
        float s = 0.f;
        for (int m = lane; m < 128; m += 32)
            s += d_memsm[m * Hh + w] * fc_w[o * 640 + 128 + 128 * j + m];
#pragma unroll
        for (int o2 = 16; o2 > 0; o2 >>= 1) s += __shfl_down_sync(0xffffffffu, s, o2);
        if (lane == 0) d_gv[i2] = s;
    } else if (gw < NG + 1024 + 8) {
        int i2 = (gw - NG - 1024) * 32 + lane;
        d_f0[i2] = fc_w[(i2 >> 7) * 640 + (i2 & 127)];
    }
}

__global__ void zero_state_kernel() {
    int i = blockIdx.x * blockDim.x + threadIdx.x;
    if (i < Bsz * Hh) {
        d_hA[i] = __float2half(0.f);
        d_hB[i] = __float2half(0.f);
    }
    if (i == 0) g_bar = 0u;
}

// convert x and W_ih[:, :256] to fp16
#define NX4 ((Bsz * Tt * DIN) / 4)      // 8,388,608
#define NW4 ((NG * DIN) / 4)            // 32,768
__global__ void convert_h_kernel(const float* __restrict__ x,
                                 const float* __restrict__ W_ih) {
    int i = blockIdx.x * blockDim.x + threadIdx.x;
    if (i < NX4) {
        float4 v = ((const float4*)x)[i];
        __half2 a = __floats2half2_rn(v.x, v.y);
        __half2 b = __floats2half2_rn(v.z, v.w);
        ((uint2*)d_xh)[i] = make_uint2(*(unsigned*)&a, *(unsigned*)&b);
    } else if (i < NX4 + NW4) {
        int j = i - NX4;
        int n = j >> 6, c4 = (j & 63) * 4;
        float4 v = *(const float4*)(W_ih + n * 768 + c4);
        __half2 a = __floats2half2_rn(v.x, v.y);
        __half2 b = __floats2half2_rn(v.z, v.w);
        *(uint2*)(d_wxh + n * DIN + c4) = make_uint2(*(unsigned*)&a, *(unsigned*)&b);
    }
}

// ---------------- gx pre-pass (fp16): d_gx[t][b][n] = x[b][t] @ Wx^T ----------------
// 64x64 C tile, 256 threads, K=256 split across 2 warp-groups (128 each).
__global__ void __launch_bounds__(256) gx_kernel_h() {
    extern __shared__ unsigned char smc[];
    __half* Ah = (__half*)smc;                      // [64][264]
    __half* Bh = (__half*)(smc + 64 * LDXH * 2);    // [64][264]
    float*  Cs = (float*)smc;                       // alias A (64x68 f32 = 17408 B)

    const int tid  = threadIdx.x;
    const int warp = tid >> 5, lane = tid & 31;
    const int grp  = warp >> 2, wl = warp & 3;
    const int wm = (wl >> 1) * 32, wn = (wl & 1) * 32;
    const int g  = lane >> 2,  t4 = lane & 3;
    const int row = tid >> 2, col = (tid & 3) * 64;  // loader: 64 halves = 8 cp16
    const int n0 = blockIdx.x * 64;
    const int r0 = blockIdx.y * 64;

    {
        const __half* xr = d_xh + (size_t)(r0 + row) * DIN + col;
        const __half* wr = d_wxh + (n0 + row) * DIN + col;
        uint32_t da = (uint32_t)__cvta_generic_to_shared(Ah + row * LDXH + col);
        uint32_t db = (uint32_t)__cvta_generic_to_shared(Bh + row * LDXH + col);
#pragma unroll
        for (int i = 0; i < 8; i++) cp16(da + i * 16, xr + i * 8);
#pragma unroll
        for (int i = 0; i < 8; i++) cp16(db + i * 16, wr + i * 8);
        cp_commit();
    }

    float acc[2][4][4];
#pragma unroll
    for (int i = 0; i < 2; i++)
#pragma unroll
        for (int j = 0; j < 4; j++)
#pragma unroll
            for (int q = 0; q < 4; q++) acc[i][j][q] = 0.f;

    cp_wait0();
    __syncthreads();

#pragma unroll
    for (int j = 0; j < 8; j++) {
        int ka = grp * 128 + j * 16 + 2 * t4;
        unsigned afr[2][4];
#pragma unroll
        for (int mi = 0; mi < 2; mi++) {
            int mr = wm + mi * 16;
            afr[mi][0] = *(const unsigned*)(Ah + (mr + g) * LDXH + ka);
            afr[mi][1] = *(const unsigned*)(Ah + (mr + g + 8) * LDXH + ka);
            afr[mi][2] = *(const unsigned*)(Ah + (mr + g) * LDXH + ka + 8);
            afr[mi][3] = *(const unsigned*)(Ah + (mr + g + 8) * LDXH + ka + 8);
        }
#pragma unroll
        for (int ni = 0; ni < 4; ni++) {
            const __half* bp = Bh + (wn + ni * 8 + g) * LDXH + ka;
            unsigned b0 = *(const unsigned*)(bp);
            unsigned b1 = *(const unsigned*)(bp + 8);
            mma16(acc[0][ni], afr[0], b0, b1);
            mma16(acc[1][ni], afr[1], b0, b1);
        }
    }
    __syncthreads();

    // cross-group reduce through Cs (fp32, aliases A)
    if (grp == 1) {
#pragma unroll
        for (int mi = 0; mi < 2; mi++)
#pragma unroll
            for (int ni = 0; ni < 4; ni++) {
                int r = wm + mi * 16 + g, cidx = wn + ni * 8 + 2 * t4;
                Cs[r * LDCc + cidx]           = acc[mi][ni][0];
                Cs[r * LDCc + cidx + 1]       = acc[mi][ni][1];
                Cs[(r + 8) * LDCc + cidx]     = acc[mi][ni][2];
                Cs[(r + 8) * LDCc + cidx + 1] = acc[mi][ni][3];
            }
    }
    __syncthreads();
    if (grp == 0) {
#pragma unroll
        for (int mi = 0; mi < 2; mi++)
#pragma unroll
            for (int ni = 0; ni < 4; ni++) {
                int r = wm + mi * 16 + g, cidx = wn + ni * 8 + 2 * t4;
                Cs[r * LDCc + cidx]           += acc[mi][ni][0];
                Cs[r * LDCc + cidx + 1]       += acc[mi][ni][1];
                Cs[(r + 8) * LDCc + cidx]     += acc[mi][ni][2];
                Cs[(r + 8) * LDCc + cidx + 1] += acc[mi][ni][3];
            }
    }
    __syncthreads();

    {
        int rr = tid >> 2, col4 = (tid & 3) * 16;
        int r = r0 + rr;
        int b = r >> 7, tt = r & 127;
        float* dst = d_gx + ((size_t)tt * Bsz + b) * NG + n0 + col4;
#pragma unroll
        for (int i = 0; i < 4; i++) {
            float* s = Cs + rr * LDCc + col4 + 4 * i;
            ((float4*)dst)[i] = make_float4(s[0], s[1], s[2], s[3]);
        }
    }
}

// ---------------- persistent fused recurrence kernel (fp16 MMA) ----------------
__global__ void __launch_bounds__(256) dnc_persistent() {
    extern __shared__ unsigned char smc[];
    __half* A1h   = (__half*)(smc + OFF_A1);    // [64][136]
    __half* A2h   = (__half*)(smc + OFF_A2);    // [16][552]
    __half* Bh    = (__half*)(smc + OFF_B);     // [64][648]
    float*  Cs    = (float*)(smc + OFF_A1);     // epilogue alias [64][68]
    float*  C2s   = (float*)(smc + OFF_A2);     // epilogue alias [4][16][68]
    float*  bias_s = (float*)(smc + OFF_BIAS);
    float*  add0_s = (float*)(smc + OFF_ADD0);

    const int tid  = threadIdx.x;
    const int warp = tid >> 5, lane = tid & 31;
    const int g = lane >> 2, t4 = lane & 3;
    const int wmh = (warp >> 2) * 32;
    const int wnh = (warp & 3) * 16;
    const int kq  = warp >> 1;
    const int wnq = (warp & 1) * 32;
    const int ui = blockIdx.x, bg = blockIdx.y;

    const int arow = tid >> 2, acol32 = (tid & 3) * 32;
    const int bArow = 256 * (arow >> 4) + bg * 16 + (arow & 15);
    const int qrow = tid >> 4, qcol32 = (tid & 15) * 32;
    const int bqoff = (bg * 16 + qrow) * 512;

    if (tid < 64) {
        int ng = (tid >> 4) * 128 + ui * 16 + (tid & 15);
        bias_s[tid] = d_bias[ng];
        add0_s[tid] = d_add0[ng];
    }
    for (int i = tid * 8; i < 64 * KW; i += 2048) {
        int row = i / KW, col = i - row * KW;
        int n   = (row >> 4) * 128 + ui * 16 + (row & 15);
        uint4 v = *(const uint4*)(d_WcTh + n * KW + col);
        *(uint4*)(Bh + row * LDBH + col) = v;
    }
    __syncthreads();

    const uint32_t a1Base = (uint32_t)__cvta_generic_to_shared(A1h + arow * LDA1H + acol32);
    const uint32_t a2Base = (uint32_t)__cvta_generic_to_shared(A2h + qrow * LDA2H + qcol32);

    float c_st[4], S_st[4];
#pragma unroll
    for (int r = 0; r < 4; r++) { c_st[r] = 0.f; S_st[r] = 0.f; }

    const int r_up = tid >> 2, uq = tid & 3;
    const int i_up = r_up & 15;
    const int b_up = 256 * (r_up >> 4) + bg * 16 + i_up;

#pragma unroll 1
    for (int t = 0; t < Tt; t++) {
        const __half* hp = (t & 1) ? d_hB : d_hA;
        __half*       hw = (t & 1) ? d_hA : d_hB;

        {
            const __half* s1 = hp + bArow * Hh + acol32;
#pragma unroll
            for (int i = 0; i < 4; i++) cp16(a1Base + i * 16, s1 + i * 8);
            const __half* s2 = hp + bqoff + qcol32;
#pragma unroll
            for (int i = 0; i < 4; i++) cp16(a2Base + i * 16, s2 + i * 8);
            cp_commit();
        }

        const float* gxp = d_gx + ((size_t)t * Bsz + b_up) * NG + ui * 16 + uq * 4;
        float4 gx0 = ((const float4*)(gxp))[0];
        float4 gx1 = ((const float4*)(gxp + 128))[0];
        float4 gx2 = ((const float4*)(gxp + 256))[0];
        float4 gx3 = ((const float4*)(gxp + 384))[0];

        float accq[4][4], acch[2][2][4];
#pragma unroll
        for (int ni = 0; ni < 4; ni++)
#pragma unroll
            for (int q = 0; q < 4; q++) accq[ni][q] = 0.f;
#pragma unroll
        for (int mi = 0; mi < 2; mi++)
#pragma unroll
            for (int ni = 0; ni < 2; ni++)
#pragma unroll
                for (int q = 0; q < 4; q++) acch[mi][ni][q] = 0.f;

        cp_wait0();
        __syncthreads();

        // gq: 16x64 C, K slice [kq*128, +128)
#pragma unroll
        for (int j = 0; j < 8; j++) {
            int ka = kq * 128 + j * 16 + 2 * t4;
            unsigned afr[4];
            afr[0] = *(const unsigned*)(A2h + g * LDA2H + ka);
            afr[1] = *(const unsigned*)(A2h + (g + 8) * LDA2H + ka);
            afr[2] = *(const unsigned*)(A2h + g * LDA2H + ka + 8);
            afr[3] = *(const unsigned*)(A2h + (g + 8) * LDA2H + ka + 8);
            int kb = 128 + kq * 128 + j * 16 + 2 * t4;
#pragma unroll
            for (int ni = 0; ni < 4; ni++) {
                const __half* bp = Bh + (wnq + ni * 8 + g) * LDBH + kb;
                unsigned b0 = *(const unsigned*)(bp);
                unsigned b1 = *(const unsigned*)(bp + 8);
                mma16(accq[ni], afr, b0, b1);
            }
        }

        // gh: 64x64 C, K=128
#pragma unroll
        for (int j = 0; j < 8; j++) {
            int ka = j * 16 + 2 * t4;
            unsigned afr[2][4];
#pragma unroll
            for (int mi = 0; mi < 2; mi++) {
                int mr = wmh + mi * 16;
                afr[mi][0] = *(const unsigned*)(A1h + (mr + g) * LDA1H + ka);
                afr[mi][1] = *(const unsigned*)(A1h + (mr + g + 8) * LDA1H + ka);
                afr[mi][2] = *(const unsigned*)(A1h + (mr + g) * LDA1H + ka + 8);
                afr[mi][3] = *(const unsigned*)(A1h + (mr + g + 8) * LDA1H + ka + 8);
            }
#pragma unroll
            for (int ni = 0; ni < 2; ni++) {
                const __half* bp = Bh + (wnh + ni * 8 + g) * LDBH + ka;
                unsigned b0 = *(const unsigned*)(bp);
                unsigned b1 = *(const unsigned*)(bp + 8);
                mma16(acch[0][ni], afr[0], b0, b1);
                mma16(acch[1][ni], afr[1], b0, b1);
            }
        }
        __syncthreads();   // smem A reads done -> aliases writable

#pragma unroll
        for (int ni = 0; ni < 4; ni++) {
            int c = wnq + ni * 8 + 2 * t4;
            float* p = C2s + kq * (16 * LDCc);
            p[g * LDCc + c]           = accq[ni][0];
            p[g * LDCc + c + 1]       = accq[ni][1];
            p[(g + 8) * LDCc + c]     = accq[ni][2];
            p[(g + 8) * LDCc + c + 1] = accq[ni][3];
        }
#pragma unroll
        for (int mi = 0; mi < 2; mi++)
#pragma unroll
            for (int ni = 0; ni < 2; ni++) {
                int r = wmh + mi * 16 + g, c = wnh + ni * 8 + 2 * t4;
                Cs[r * LDCc + c]           = acch[mi][ni][0];
                Cs[r * LDCc + c + 1]       = acch[mi][ni][1];
                Cs[(r + 8) * LDCc + c]     = acch[mi][ni][2];
                Cs[(r + 8) * LDCc + c + 1] = acch[mi][ni][3];
            }
        __syncthreads();

        // pre-reduce the 4 gq partials into C2s[0]
        {
            int id0 = tid * 4;
#pragma unroll
            for (int e = 0; e < 4; e++) {
                int id = id0 + e, rr = id >> 6, cc = id & 63;
                int o = rr * LDCc + cc;
                C2s[o] += C2s[(16 * LDCc) + o] + C2s[2 * (16 * LDCc) + o]
                        + C2s[3 * (16 * LDCc) + o];
            }
        }
        __syncthreads();

        // fused LSTM update
        {
            const float* c2p = C2s + i_up * LDCc;
            const float* csp = Cs + r_up * LDCc;
            const float* gxa[4] = { (const float*)&gx0, (const float*)&gx1,
                                    (const float*)&gx2, (const float*)&gx3 };
            float hv[4];
#pragma unroll
            for (int e = 0; e < 4; e++) {
                int ul = uq * 4 + e;
                float ig  = csp[ul]      + c2p[ul]      + bias_s[ul]      + gxa[0][e];
                float fg  = csp[16 + ul] + c2p[16 + ul] + bias_s[16 + ul] + gxa[1][e];
                float gg2 = csp[32 + ul] + c2p[32 + ul] + bias_s[32 + ul] + gxa[2][e];
                float og  = csp[48 + ul] + c2p[48 + ul] + bias_s[48 + ul] + gxa[3][e];
                if (t == 0) {
                    ig  += add0_s[ul];      fg += add0_s[16 + ul];
                    gg2 += add0_s[32 + ul]; og += add0_s[48 + ul];
                }
                float si = sigm_f(ig);
                float sf = sigm_f(fg);
                float so = sigm_f(og);
                float c  = sf * c_st[e] + si * tanh_f(gg2);
                float h  = so * tanh_f(c);
                c_st[e] = c;
                S_st[e] += h;
                hv[e] = h;
            }
            __half2 p0 = __floats2half2_rn(hv[0], hv[1]);
            __half2 p1 = __floats2half2_rn(hv[2], hv[3]);
            __half* hwp = hw + b_up * Hh + ui * 16 + uq * 4;
            *(uint2*)hwp = make_uint2(*(unsigned*)&p0, *(unsigned*)&p1);
        }

        // release/acquire grid barrier (no threadfence needed)
        __syncthreads();
        if (tid == 0) {
            red_release_add(&g_bar, 1u);
            unsigned target = (unsigned)NBLK * (unsigned)(t + 1);
            while (ld_acquire(&g_bar) < target) { }
        }
        __syncthreads();
    }

    {
        float* Sp = d_S + b_up * Hh + ui * 16 + uq * 4;
        *(float4*)Sp = make_float4(S_st[0], S_st[1], S_st[2], S_st[3]);
    }
}

// ---------------- final output: mean over t, linear in S ----------------
__global__ void final_out_kernel(float* __restrict__ out, const float* __restrict__ fc_b) {
    int idx = blockIdx.x * blockDim.x + threadIdx.x;
    if (idx >= Bsz * 2) return;
    int b = idx >> 1, o = idx & 1;
    const float* Sb = d_S + b * Hh;
    const float* f0 = d_f0 + o * Hh;
    float s = 0.f;
#pragma unroll 8
    for (int w = 0; w < Hh; w++) s += Sb[w] * f0[w];
#pragma unroll
    for (int j = 0; j < 4; j++) {
        int bs = (4 * b + j) & (Bsz - 1);
        const float* Sp = d_S + bs * Hh;
        const float* gp = d_gv + o * 512 + j * Hh;
#pragma unroll 8
        for (int w = 0; w < Hh; w++) s += Sp[w] * gp[w];
    }
    out[idx] = s * (1.f / (float)Tt) + fc_b[o];
}

// ---------------- launch ----------------
extern "C" void kernel_launch(void* const* d_in, const int* in_sizes, int n_in,
                              void* d_out, int out_size) {
    const float* x      = (const float*)d_in[0];
    const float* memory = (const float*)d_in[1];
    const float* rv0    = (const float*)d_in[2];
    const float* W_ih   = (const float*)d_in[3];
    const float* W_hh   = (const float*)d_in[4];
    const float* b_ih   = (const float*)d_in[5];
    const float* b_hh   = (const float*)d_in[6];
    const float* fc_w   = (const float*)d_in[7];
    const float* fc_b   = (const float*)d_in[8];
    float* out = (float*)d_out;

    const int smem_pers = SMEM_BYTES;                // 118,528 B
    const int smem_gx   = 2 * 64 * LDXH * 2;         // 67,584 B
    cudaFuncSetAttribute(dnc_persistent,
                         cudaFuncAttributeMaxDynamicSharedMemorySize, smem_pers);
    cudaFuncSetAttribute(gx_kernel_h,
                         cudaFuncAttributeMaxDynamicSharedMemorySize, smem_gx);

    zero_state_kernel<<<(Bsz * Hh + 255) / 256, 256>>>();
    softmax_kernel<<<Hh, Hh>>>(memory);
    convert_h_kernel<<<(NX4 + NW4 + 255) / 256, 256>>>(x, W_ih);
    build_wct2_kernel<<<(NG * KW + 255) / 256, 256>>>(W_ih, W_hh);
    build_misc2_kernel<<<193, 256>>>(W_ih, rv0, b_ih, b_hh, fc_w);

    gx_kernel_h<<<dim3(8, (Bsz * Tt) / 64), 256, smem_gx>>>();

    dnc_persistent<<<dim3(8, 16), 256, smem_pers>>>();

    final_out_kernel<<<(Bsz * 2 + 255) / 256, 256>>>(out, fc_b);
}